// round 2
// baseline (speedup 1.0000x reference)
#include <cuda_runtime.h>

// Problem constants: B=4, S=1024, D=1024 -> ROWS = B*S = 4096
#define D_DIM 1024
#define ROWS  4096

// Scratch: fused weight W = Wo @ Wv (row-major [o][j]) and fused bias.
__device__ float g_W[D_DIM * D_DIM];
__device__ float g_bias[D_DIM];

// ---- Tiled fp32 GEMM config ----
#define BM 64
#define BN 64
#define BK 16
#define TM 4
#define TN 4
// threads per block = (BM/TM)*(BN/TN) = 256

// Kernel A (NN): g_W[m][n] = sum_k Wo[m][k] * Wv[k][n]   (M=N=K=1024)
__global__ void __launch_bounds__(256)
fuse_weights_nn(const float* __restrict__ A, const float* __restrict__ B) {
    __shared__ float As[BK][BM + 1];
    __shared__ float Bs[BK][BN];

    const int tid = threadIdx.x;
    const int m0 = blockIdx.y * BM;
    const int n0 = blockIdx.x * BN;
    const int tm = (tid / 16) * TM;
    const int tn = (tid % 16) * TN;
    const int K = D_DIM, N = D_DIM;

    float acc[TM][TN] = {};

    for (int k0 = 0; k0 < K; k0 += BK) {
        // A tile: 64 rows x 16 k, coalesced over k
        {
            const int k = tid % BK;       // 0..15
            const int m = tid / BK;       // 0..15
            #pragma unroll
            for (int i = 0; i < 4; i++)
                As[k][m + 16 * i] = A[(m0 + m + 16 * i) * K + k0 + k];
        }
        // B tile: 16 k x 64 n, coalesced over n
        {
            const int n = tid % BN;       // 0..63
            const int k = tid / BN;       // 0..3
            #pragma unroll
            for (int i = 0; i < 4; i++)
                Bs[k + 4 * i][n] = B[(k0 + k + 4 * i) * N + n0 + n];
        }
        __syncthreads();

        #pragma unroll
        for (int k = 0; k < BK; k++) {
            float a[TM], b[TN];
            #pragma unroll
            for (int i = 0; i < TM; i++) a[i] = As[k][tm + i];
            #pragma unroll
            for (int j = 0; j < TN; j++) b[j] = Bs[k][tn + j];
            #pragma unroll
            for (int i = 0; i < TM; i++)
                #pragma unroll
                for (int j = 0; j < TN; j++)
                    acc[i][j] += a[i] * b[j];
        }
        __syncthreads();
    }

    #pragma unroll
    for (int i = 0; i < TM; i++)
        #pragma unroll
        for (int j = 0; j < TN; j++)
            g_W[(m0 + tm + i) * N + n0 + tn + j] = acc[i][j];
}

// Fused bias: g_bias[o] = bo[o] + sum_k Wo[o][k] * bv[k]
__global__ void fuse_bias(const float* __restrict__ Wo,
                          const float* __restrict__ bv,
                          const float* __restrict__ bo) {
    const int o = blockIdx.x * blockDim.x + threadIdx.x;
    if (o < D_DIM) {
        float s = bo[o];
        const float* row = Wo + (size_t)o * D_DIM;
        #pragma unroll 8
        for (int k = 0; k < D_DIM; k++) s += row[k] * bv[k];
        g_bias[o] = s;
    }
}

// Kernel B (NT): out[m][n] = sum_k V[m][k] * g_W[n][k] + g_bias[n]
// M=4096, N=1024, K=1024. Both operands contiguous along k.
__global__ void __launch_bounds__(256)
out_gemm_nt(const float* __restrict__ V, float* __restrict__ C) {
    __shared__ float As[BK][BM + 1];
    __shared__ float Bs[BK][BN + 1];

    const int tid = threadIdx.x;
    const int m0 = blockIdx.y * BM;
    const int n0 = blockIdx.x * BN;
    const int tm = (tid / 16) * TM;
    const int tn = (tid % 16) * TN;
    const int K = D_DIM, N = D_DIM;

    float acc[TM][TN] = {};

    for (int k0 = 0; k0 < K; k0 += BK) {
        // A (V) tile: 64 m x 16 k, coalesced over k
        {
            const int k = tid % BK;
            const int m = tid / BK;
            #pragma unroll
            for (int i = 0; i < 4; i++)
                As[k][m + 16 * i] = V[(m0 + m + 16 * i) * K + k0 + k];
        }
        // B (W) tile, NT: Bs[k][n] = g_W[(n0+n)*K + k0+k], coalesced over k
        {
            const int k = tid % BK;
            const int n = tid / BK;      // 0..15
            #pragma unroll
            for (int i = 0; i < 4; i++)
                Bs[k][n + 16 * i] = g_W[(size_t)(n0 + n + 16 * i) * K + k0 + k];
        }
        __syncthreads();

        #pragma unroll
        for (int k = 0; k < BK; k++) {
            float a[TM], b[TN];
            #pragma unroll
            for (int i = 0; i < TM; i++) a[i] = As[k][tm + i];
            #pragma unroll
            for (int j = 0; j < TN; j++) b[j] = Bs[k][tn + j];
            #pragma unroll
            for (int i = 0; i < TM; i++)
                #pragma unroll
                for (int j = 0; j < TN; j++)
                    acc[i][j] += a[i] * b[j];
        }
        __syncthreads();
    }

    #pragma unroll
    for (int i = 0; i < TM; i++) {
        #pragma unroll
        for (int j = 0; j < TN; j++) {
            const int n = n0 + tn + j;
            C[(size_t)(m0 + tm + i) * N + n] = acc[i][j] + g_bias[n];
        }
    }
}

extern "C" void kernel_launch(void* const* d_in, const int* in_sizes, int n_in,
                              void* d_out, int out_size) {
    // metadata order: 0 query, 1 key, 2 value, 3 mask,
    //                 4 Wq, 5 bq, 6 Wk, 7 bk, 8 Wv, 9 bv, 10 Wo, 11 bo
    const float* value = (const float*)d_in[2];
    const float* Wv    = (const float*)d_in[8];
    const float* bv    = (const float*)d_in[9];
    const float* Wo    = (const float*)d_in[10];
    const float* bo    = (const float*)d_in[11];
    float* out = (float*)d_out;

    // 1) W = Wo @ Wv  (1024x1024x1024)
    {
        dim3 grid(D_DIM / BN, D_DIM / BM);
        fuse_weights_nn<<<grid, 256>>>(Wo, Wv);
    }
    // 2) b' = Wo @ bv + bo
    fuse_bias<<<D_DIM / 256, 256>>>(Wo, bv, bo);

    // 3) out = value @ W^T + b'  (4096x1024x1024)
    {
        dim3 grid(D_DIM / BN, ROWS / BM);
        out_gemm_nt<<<grid, 256>>>(value, out);
    }
}

// round 4
// speedup vs baseline: 2.6217x; 2.6217x over previous
#include <cuda_runtime.h>
#include <cuda_bf16.h>
#include <cstdint>
#include <cstddef>

#define D_DIM 1024
#define ROWS  4096   // B*S = 4*1024

// ------------------------- device scratch -------------------------
__device__ float         g_W[D_DIM * D_DIM];      // fused W = Wo @ Wv (fp32)
__device__ float         g_bias[D_DIM];           // fused bias = Wo@bv + bo
__device__ __nv_bfloat16 g_Vhi[ROWS * D_DIM];
__device__ __nv_bfloat16 g_Vlo[ROWS * D_DIM];
__device__ __nv_bfloat16 g_Aohi[D_DIM * D_DIM];   // Wo split  (row-major [m][k])
__device__ __nv_bfloat16 g_Aolo[D_DIM * D_DIM];
__device__ __nv_bfloat16 g_Bvhi[D_DIM * D_DIM];   // Wv^T split (row-major [n][k])
__device__ __nv_bfloat16 g_Bvlo[D_DIM * D_DIM];
__device__ __nv_bfloat16 g_Whi[D_DIM * D_DIM];    // W split (row-major [n][k])
__device__ __nv_bfloat16 g_Wlo[D_DIM * D_DIM];

// ------------------------- helpers -------------------------
__device__ __forceinline__ uint32_t smem_u32(const void* p) {
    uint32_t a;
    asm("{ .reg .u64 t; cvta.to.shared.u64 t, %1; cvt.u32.u64 %0, t; }"
        : "=r"(a) : "l"(p));
    return a;
}

__device__ __forceinline__ void ldmatrix_x4(uint32_t* r, uint32_t addr) {
    asm volatile("ldmatrix.sync.aligned.m8n8.x4.shared.b16 {%0,%1,%2,%3}, [%4];"
                 : "=r"(r[0]), "=r"(r[1]), "=r"(r[2]), "=r"(r[3]) : "r"(addr));
}

__device__ __forceinline__ void mma_bf16(float* d, const uint32_t* a,
                                         const uint32_t* b) {
    asm volatile(
        "mma.sync.aligned.m16n8k16.row.col.f32.bf16.bf16.f32 "
        "{%0,%1,%2,%3}, {%4,%5,%6,%7}, {%8,%9}, {%0,%1,%2,%3};"
        : "+f"(d[0]), "+f"(d[1]), "+f"(d[2]), "+f"(d[3])
        : "r"(a[0]), "r"(a[1]), "r"(a[2]), "r"(a[3]), "r"(b[0]), "r"(b[1]));
}

__device__ __forceinline__ void cp_async16(uint32_t dst, const void* src) {
    asm volatile("cp.async.cg.shared.global [%0], [%1], 16;"
                 :: "r"(dst), "l"(src) : "memory");
}

// ------------------------- conversion kernels -------------------------
__device__ __forceinline__ uint32_t pack_split2(float a, float b,
                                                float& ra, float& rb) {
    __nv_bfloat16 ha = __float2bfloat16(a);
    __nv_bfloat16 hb = __float2bfloat16(b);
    ra = a - __bfloat162float(ha);
    rb = b - __bfloat162float(hb);
    __nv_bfloat162 v(ha, hb);
    return *reinterpret_cast<uint32_t*>(&v);
}

__global__ void split_bf16_v4(const float4* __restrict__ in,
                              uint32_t* __restrict__ hi,
                              uint32_t* __restrict__ lo, int n4) {
    int i = blockIdx.x * blockDim.x + threadIdx.x;
    if (i >= n4) return;
    float4 x = in[i];
    float r0, r1, r2, r3;
    uint32_t h0 = pack_split2(x.x, x.y, r0, r1);
    uint32_t h1 = pack_split2(x.z, x.w, r2, r3);
    __nv_bfloat162 l0(__float2bfloat16(r0), __float2bfloat16(r1));
    __nv_bfloat162 l1(__float2bfloat16(r2), __float2bfloat16(r3));
    hi[2 * i]     = h0;
    hi[2 * i + 1] = h1;
    lo[2 * i]     = *reinterpret_cast<uint32_t*>(&l0);
    lo[2 * i + 1] = *reinterpret_cast<uint32_t*>(&l1);
}

// Wv[k][n] -> out_hi/lo[n][k]  (transpose + split)
__global__ void transpose_split(const float* __restrict__ in,
                                __nv_bfloat16* __restrict__ hi,
                                __nv_bfloat16* __restrict__ lo) {
    __shared__ float tile[32][33];
    int x = blockIdx.x * 32 + threadIdx.x;   // input col (n)
    int y = blockIdx.y * 32;                 // input row base (k)
    #pragma unroll
    for (int j = threadIdx.y; j < 32; j += 8)
        tile[j][threadIdx.x] = in[(size_t)(y + j) * D_DIM + x];
    __syncthreads();
    int ox = blockIdx.y * 32 + threadIdx.x;  // output col (k)
    int oyb = blockIdx.x * 32;               // output row base (n)
    #pragma unroll
    for (int j = threadIdx.y; j < 32; j += 8) {
        float v = tile[threadIdx.x][j];
        __nv_bfloat16 h = __float2bfloat16(v);
        size_t o = (size_t)(oyb + j) * D_DIM + ox;
        hi[o] = h;
        lo[o] = __float2bfloat16(v - __bfloat162float(h));
    }
}

// g_bias[o] = bo[o] + sum_k Wo[o][k] * bv[k]   (warp per row, coalesced)
__global__ void fuse_bias(const float* __restrict__ Wo,
                          const float* __restrict__ bv,
                          const float* __restrict__ bo) {
    const int wid = threadIdx.x >> 5;
    const int lid = threadIdx.x & 31;
    const int row = blockIdx.x * 8 + wid;
    const float* r = Wo + (size_t)row * D_DIM;
    float s = 0.f;
    #pragma unroll 4
    for (int k = lid; k < D_DIM; k += 32) s += r[k] * bv[k];
    #pragma unroll
    for (int o = 16; o > 0; o >>= 1)
        s += __shfl_down_sync(0xFFFFFFFFu, s, o);
    if (lid == 0) g_bias[row] = s + bo[row];
}

// ------------------------- mma.sync split-bf16 NT GEMM -------------------------
// C[m][n] = sum_k A[m][k]*B[n][k], 3 passes (hi*hi, lo*hi, hi*lo), fp32 accum.
// CTA 128x128, BK=32, 256 threads, warp tile 64x32 (2x4 warps).
#define BK      32
#define LDS_S   40                     // padded row: 32 bf16 + 8 -> 80 bytes
#define NTK     (D_DIM / BK)           // 32
#define TILE_B  (128 * LDS_S * 2)      // 10240 bytes per buffer per operand

__global__ void __launch_bounds__(256, 2)
gemm_nt_split(const __nv_bfloat16* __restrict__ Ahi,
              const __nv_bfloat16* __restrict__ Alo,
              const __nv_bfloat16* __restrict__ Bhi,
              const __nv_bfloat16* __restrict__ Blo,
              float* __restrict__ C,
              const float* __restrict__ bias, int use_bias) {
    __shared__ __align__(128) __nv_bfloat16 As[2][128][LDS_S];
    __shared__ __align__(128) __nv_bfloat16 Bs[2][128][LDS_S];

    const int tid = threadIdx.x;
    const int wid = tid >> 5;
    const int lid = tid & 31;
    const int wm  = wid >> 2;          // 0..1 -> 64-row slab
    const int wn  = wid & 3;           // 0..3 -> 32-col slab
    const int m0  = blockIdx.y * 128;
    const int n0  = blockIdx.x * 128;

    const uint32_t sA = smem_u32(&As[0][0][0]);
    const uint32_t sB = smem_u32(&Bs[0][0][0]);

    const __nv_bfloat16* Aptr[3] = {Ahi, Alo, Ahi};
    const __nv_bfloat16* Bptr[3] = {Bhi, Bhi, Blo};

    // ldmatrix lane geometry (same for A and B, non-transposed)
    const int mat  = lid >> 3;                  // 0..3
    const int mrow = ((mat & 1) << 3) + (lid & 7);
    const int mcolb = (mat >> 1) << 4;          // 0 or 16 bytes

    // cp.async assignment: 512 16B-chunks per operand, 2 per thread
    // chunk id -> row = id/4, c = id%4 (16B within 64B row payload)
    const int id0 = tid, id1 = tid + 256;

    float acc[4][4][4];
    #pragma unroll
    for (int i = 0; i < 4; i++)
        #pragma unroll
        for (int j = 0; j < 4; j++)
            #pragma unroll
            for (int q = 0; q < 4; q++) acc[i][j][q] = 0.f;

    const int T = 3 * NTK;   // 96

    auto issue_load = [&](int buf, int t) {
        const int pass = t / NTK;
        const int k0   = (t % NTK) * BK;
        const __nv_bfloat16* Ag = Aptr[pass] + (size_t)m0 * D_DIM + k0;
        const __nv_bfloat16* Bg = Bptr[pass] + (size_t)n0 * D_DIM + k0;
        const uint32_t bufA = sA + buf * TILE_B;
        const uint32_t bufB = sB + buf * TILE_B;
        {
            const int r = id0 >> 2, c = id0 & 3;
            cp_async16(bufA + r * 80 + c * 16, Ag + (size_t)r * D_DIM + c * 8);
            cp_async16(bufB + r * 80 + c * 16, Bg + (size_t)r * D_DIM + c * 8);
        }
        {
            const int r = id1 >> 2, c = id1 & 3;
            cp_async16(bufA + r * 80 + c * 16, Ag + (size_t)r * D_DIM + c * 8);
            cp_async16(bufB + r * 80 + c * 16, Bg + (size_t)r * D_DIM + c * 8);
        }
        asm volatile("cp.async.commit_group;" ::: "memory");
    };

    issue_load(0, 0);

    for (int t = 0; t < T; t++) {
        const int buf = t & 1;
        if (t + 1 < T) {
            issue_load(buf ^ 1, t + 1);
            asm volatile("cp.async.wait_group 1;" ::: "memory");
        } else {
            asm volatile("cp.async.wait_group 0;" ::: "memory");
        }
        __syncthreads();

        const uint32_t bufA = sA + buf * TILE_B;
        const uint32_t bufB = sB + buf * TILE_B;

        #pragma unroll
        for (int kk = 0; kk < 2; kk++) {          // two k16 steps
            uint32_t a[4][4];
            uint32_t b[4][2];
            #pragma unroll
            for (int mi = 0; mi < 4; mi++) {
                uint32_t addr = bufA +
                    (uint32_t)(wm * 64 + mi * 16 + mrow) * 80 + mcolb + kk * 32;
                ldmatrix_x4(a[mi], addr);
            }
            #pragma unroll
            for (int nj = 0; nj < 2; nj++) {
                uint32_t r[4];
                uint32_t addr = bufB +
                    (uint32_t)(wn * 32 + nj * 16 + mrow) * 80 + mcolb + kk * 32;
                ldmatrix_x4(r, addr);
                b[nj * 2][0]     = r[0]; b[nj * 2][1]     = r[2];
                b[nj * 2 + 1][0] = r[1]; b[nj * 2 + 1][1] = r[3];
            }
            #pragma unroll
            for (int mi = 0; mi < 4; mi++)
                #pragma unroll
                for (int ni = 0; ni < 4; ni++)
                    mma_bf16(acc[mi][ni], a[mi], b[ni]);
        }
        __syncthreads();
    }

    // ---- epilogue ----
    const int trow = lid >> 2;
    const int tcol = (lid & 3) * 2;
    #pragma unroll
    for (int mi = 0; mi < 4; mi++) {
        const int row = m0 + wm * 64 + mi * 16 + trow;
        #pragma unroll
        for (int ni = 0; ni < 4; ni++) {
            const int col = n0 + wn * 32 + ni * 8 + tcol;
            float b0 = 0.f, b1 = 0.f;
            if (use_bias) { b0 = bias[col]; b1 = bias[col + 1]; }
            float2 v0 = {acc[mi][ni][0] + b0, acc[mi][ni][1] + b1};
            float2 v1 = {acc[mi][ni][2] + b0, acc[mi][ni][3] + b1};
            *reinterpret_cast<float2*>(&C[(size_t)row * D_DIM + col]) = v0;
            *reinterpret_cast<float2*>(&C[(size_t)(row + 8) * D_DIM + col]) = v1;
        }
    }
}

// ------------------------- host launcher -------------------------
extern "C" void kernel_launch(void* const* d_in, const int* in_sizes, int n_in,
                              void* d_out, int out_size) {
    // 0 query, 1 key, 2 value, 3 mask, 4 Wq, 5 bq, 6 Wk, 7 bk, 8 Wv, 9 bv, 10 Wo, 11 bo
    const float* value = (const float*)d_in[2];
    const float* Wv    = (const float*)d_in[8];
    const float* bv    = (const float*)d_in[9];
    const float* Wo    = (const float*)d_in[10];
    const float* bo    = (const float*)d_in[11];
    float* out = (float*)d_out;

    void *pW, *pbias, *pVhi, *pVlo, *pAohi, *pAolo, *pBvhi, *pBvlo, *pWhi, *pWlo;
    cudaGetSymbolAddress(&pW, g_W);
    cudaGetSymbolAddress(&pbias, g_bias);
    cudaGetSymbolAddress(&pVhi, g_Vhi);
    cudaGetSymbolAddress(&pVlo, g_Vlo);
    cudaGetSymbolAddress(&pAohi, g_Aohi);
    cudaGetSymbolAddress(&pAolo, g_Aolo);
    cudaGetSymbolAddress(&pBvhi, g_Bvhi);
    cudaGetSymbolAddress(&pBvlo, g_Bvlo);
    cudaGetSymbolAddress(&pWhi, g_Whi);
    cudaGetSymbolAddress(&pWlo, g_Wlo);

    // 1) conversions
    {
        int n4 = (D_DIM * D_DIM) / 4;
        split_bf16_v4<<<(n4 + 255) / 256, 256>>>((const float4*)Wo,
                                                 (uint32_t*)pAohi, (uint32_t*)pAolo, n4);
    }
    {
        dim3 blk(32, 8), grd(D_DIM / 32, D_DIM / 32);
        transpose_split<<<grd, blk>>>(Wv, (__nv_bfloat16*)pBvhi, (__nv_bfloat16*)pBvlo);
    }
    {
        int n4 = (ROWS * D_DIM) / 4;
        split_bf16_v4<<<(n4 + 255) / 256, 256>>>((const float4*)value,
                                                 (uint32_t*)pVhi, (uint32_t*)pVlo, n4);
    }
    fuse_bias<<<D_DIM / 8, 256>>>(Wo, bv, bo);

    // 2) W = Wo @ Wv^T-form (tensor, M=N=K=1024) -> fp32 scratch
    {
        dim3 grid(D_DIM / 128, D_DIM / 128);
        gemm_nt_split<<<grid, 256>>>(
            (const __nv_bfloat16*)pAohi, (const __nv_bfloat16*)pAolo,
            (const __nv_bfloat16*)pBvhi, (const __nv_bfloat16*)pBvlo,
            (float*)pW, (const float*)pbias, 0);
    }

    // 3) split W
    {
        int n4 = (D_DIM * D_DIM) / 4;
        split_bf16_v4<<<(n4 + 255) / 256, 256>>>((const float4*)pW,
                                                 (uint32_t*)pWhi, (uint32_t*)pWlo, n4);
    }

    // 4) out = value @ W^T + bias (tensor, M=4096)
    {
        dim3 grid(D_DIM / 128, ROWS / 128);
        gemm_nt_split<<<grid, 256>>>(
            (const __nv_bfloat16*)pVhi, (const __nv_bfloat16*)pVlo,
            (const __nv_bfloat16*)pWhi, (const __nv_bfloat16*)pWlo,
            out, (const float*)pbias, 1);
    }
}

// round 5
// speedup vs baseline: 3.0999x; 1.1824x over previous
#include <cuda_runtime.h>
#include <cuda_bf16.h>
#include <cstdint>
#include <cstddef>

#define D_DIM 1024
#define ROWS  4096   // B*S = 4*1024

// ------------------------- device scratch -------------------------
__device__ float         g_W0[D_DIM * D_DIM];     // GEMM1 pass partials (fp32)
__device__ float         g_W1[D_DIM * D_DIM];
__device__ float         g_W2[D_DIM * D_DIM];
__device__ float         g_bias[D_DIM];           // fused bias = Wo@bv + bo
__device__ __nv_bfloat16 g_Vhi[ROWS * D_DIM];
__device__ __nv_bfloat16 g_Vlo[ROWS * D_DIM];
__device__ __nv_bfloat16 g_Aohi[D_DIM * D_DIM];   // Wo split  (row-major [m][k])
__device__ __nv_bfloat16 g_Aolo[D_DIM * D_DIM];
__device__ __nv_bfloat16 g_Bvhi[D_DIM * D_DIM];   // Wv^T split (row-major [n][k])
__device__ __nv_bfloat16 g_Bvlo[D_DIM * D_DIM];
__device__ __nv_bfloat16 g_Whi[D_DIM * D_DIM];    // W split (row-major [n][k])
__device__ __nv_bfloat16 g_Wlo[D_DIM * D_DIM];

// ------------------------- helpers -------------------------
__device__ __forceinline__ uint32_t smem_u32(const void* p) {
    uint32_t a;
    asm("{ .reg .u64 t; cvta.to.shared.u64 t, %1; cvt.u32.u64 %0, t; }"
        : "=r"(a) : "l"(p));
    return a;
}

__device__ __forceinline__ void ldmatrix_x4(uint32_t* r, uint32_t addr) {
    asm volatile("ldmatrix.sync.aligned.m8n8.x4.shared.b16 {%0,%1,%2,%3}, [%4];"
                 : "=r"(r[0]), "=r"(r[1]), "=r"(r[2]), "=r"(r[3]) : "r"(addr));
}

__device__ __forceinline__ void mma_bf16(float* d, const uint32_t* a,
                                         const uint32_t* b) {
    asm volatile(
        "mma.sync.aligned.m16n8k16.row.col.f32.bf16.bf16.f32 "
        "{%0,%1,%2,%3}, {%4,%5,%6,%7}, {%8,%9}, {%0,%1,%2,%3};"
        : "+f"(d[0]), "+f"(d[1]), "+f"(d[2]), "+f"(d[3])
        : "r"(a[0]), "r"(a[1]), "r"(a[2]), "r"(a[3]), "r"(b[0]), "r"(b[1]));
}

__device__ __forceinline__ void cp_async16(uint32_t dst, const void* src) {
    asm volatile("cp.async.cg.shared.global [%0], [%1], 16;"
                 :: "r"(dst), "l"(src) : "memory");
}

// ------------------------- conversion kernels -------------------------
__device__ __forceinline__ uint32_t pack_split2(float a, float b,
                                                float& ra, float& rb) {
    __nv_bfloat16 ha = __float2bfloat16(a);
    __nv_bfloat16 hb = __float2bfloat16(b);
    ra = a - __bfloat162float(ha);
    rb = b - __bfloat162float(hb);
    __nv_bfloat162 v(ha, hb);
    return *reinterpret_cast<uint32_t*>(&v);
}

__global__ void split_bf16_v4(const float4* __restrict__ in,
                              uint32_t* __restrict__ hi,
                              uint32_t* __restrict__ lo, int n4) {
    int i = blockIdx.x * blockDim.x + threadIdx.x;
    if (i >= n4) return;
    float4 x = in[i];
    float r0, r1, r2, r3;
    uint32_t h0 = pack_split2(x.x, x.y, r0, r1);
    uint32_t h1 = pack_split2(x.z, x.w, r2, r3);
    __nv_bfloat162 l0(__float2bfloat16(r0), __float2bfloat16(r1));
    __nv_bfloat162 l1(__float2bfloat16(r2), __float2bfloat16(r3));
    hi[2 * i]     = h0;
    hi[2 * i + 1] = h1;
    lo[2 * i]     = *reinterpret_cast<uint32_t*>(&l0);
    lo[2 * i + 1] = *reinterpret_cast<uint32_t*>(&l1);
}

// W = W0 + W1 + W2 (fp32), then split into bf16 hi/lo.
__global__ void sum_split_v4(const float4* __restrict__ W0,
                             const float4* __restrict__ W1,
                             const float4* __restrict__ W2,
                             uint32_t* __restrict__ hi,
                             uint32_t* __restrict__ lo, int n4) {
    int i = blockIdx.x * blockDim.x + threadIdx.x;
    if (i >= n4) return;
    float4 a = W0[i], b = W1[i], c = W2[i];
    float4 x;
    x.x = a.x + b.x + c.x;
    x.y = a.y + b.y + c.y;
    x.z = a.z + b.z + c.z;
    x.w = a.w + b.w + c.w;
    float r0, r1, r2, r3;
    uint32_t h0 = pack_split2(x.x, x.y, r0, r1);
    uint32_t h1 = pack_split2(x.z, x.w, r2, r3);
    __nv_bfloat162 l0(__float2bfloat16(r0), __float2bfloat16(r1));
    __nv_bfloat162 l1(__float2bfloat16(r2), __float2bfloat16(r3));
    hi[2 * i]     = h0;
    hi[2 * i + 1] = h1;
    lo[2 * i]     = *reinterpret_cast<uint32_t*>(&l0);
    lo[2 * i + 1] = *reinterpret_cast<uint32_t*>(&l1);
}

// Wv[k][n] -> out_hi/lo[n][k]  (transpose + split)
__global__ void transpose_split(const float* __restrict__ in,
                                __nv_bfloat16* __restrict__ hi,
                                __nv_bfloat16* __restrict__ lo) {
    __shared__ float tile[32][33];
    int x = blockIdx.x * 32 + threadIdx.x;   // input col (n)
    int y = blockIdx.y * 32;                 // input row base (k)
    #pragma unroll
    for (int j = threadIdx.y; j < 32; j += 8)
        tile[j][threadIdx.x] = in[(size_t)(y + j) * D_DIM + x];
    __syncthreads();
    int ox = blockIdx.y * 32 + threadIdx.x;  // output col (k)
    int oyb = blockIdx.x * 32;               // output row base (n)
    #pragma unroll
    for (int j = threadIdx.y; j < 32; j += 8) {
        float v = tile[threadIdx.x][j];
        __nv_bfloat16 h = __float2bfloat16(v);
        size_t o = (size_t)(oyb + j) * D_DIM + ox;
        hi[o] = h;
        lo[o] = __float2bfloat16(v - __bfloat162float(h));
    }
}

// g_bias[o] = bo[o] + sum_k Wo[o][k] * bv[k]   (warp per row, float4 loads)
__global__ void fuse_bias(const float* __restrict__ Wo,
                          const float* __restrict__ bv,
                          const float* __restrict__ bo) {
    const int wid = threadIdx.x >> 5;
    const int lid = threadIdx.x & 31;
    const int row = blockIdx.x * 16 + wid;
    const float4* r4 = (const float4*)(Wo + (size_t)row * D_DIM);
    const float4* b4 = (const float4*)bv;
    float s = 0.f;
    #pragma unroll
    for (int i = 0; i < 8; i++) {
        float4 a = r4[lid + i * 32];
        float4 b = b4[lid + i * 32];
        s += a.x * b.x + a.y * b.y + a.z * b.z + a.w * b.w;
    }
    #pragma unroll
    for (int o = 16; o > 0; o >>= 1)
        s += __shfl_down_sync(0xFFFFFFFFu, s, o);
    if (lid == 0) g_bias[row] = s + bo[row];
}

// ------------------------- mma.sync split-bf16 NT GEMM -------------------------
// C[m][n] = sum_k A[m][k]*B[n][k], fp32 accum.
// ZSPLIT=false: 3 passes in-CTA (hi*hi, lo*hi, hi*lo).
// ZSPLIT=true : blockIdx.z selects the pass; C offset by z*zstride.
// CTA 128x128, BK=32, 256 threads (8 warps, warp tile 64x32), 4-stage cp.async.
#define BK       32
#define NTK      (D_DIM / BK)            // 32
#define STAGES   4
#define STAGE_B  20480                   // (128*40 + 128*40) * 2 bytes
#define SMEM_SZ  (STAGES * STAGE_B)      // 81920

template <bool ZSPLIT>
__global__ void __launch_bounds__(256, 2)
gemm_nt_split(const __nv_bfloat16* __restrict__ Ahi,
              const __nv_bfloat16* __restrict__ Alo,
              const __nv_bfloat16* __restrict__ Bhi,
              const __nv_bfloat16* __restrict__ Blo,
              float* __restrict__ C, size_t zstride,
              const float* __restrict__ bias, int use_bias) {
    extern __shared__ __align__(128) char smem[];

    const int tid = threadIdx.x;
    const int wid = tid >> 5;
    const int lid = tid & 31;
    const int wm  = wid >> 2;          // 0..1 -> 64-row slab
    const int wn  = wid & 3;           // 0..3 -> 32-col slab
    const int m0  = blockIdx.y * 128;
    const int n0  = blockIdx.x * 128;

    const uint32_t sbase = smem_u32(smem);

    const __nv_bfloat16* Aptr[3] = {Ahi, Alo, Ahi};
    const __nv_bfloat16* Bptr[3] = {Bhi, Bhi, Blo};

    if (ZSPLIT) C += (size_t)blockIdx.z * zstride;
    const int zpass = ZSPLIT ? blockIdx.z : 0;
    const int T = ZSPLIT ? NTK : 3 * NTK;

    // ldmatrix lane geometry
    const int mat   = lid >> 3;
    const int mrow  = ((mat & 1) << 3) + (lid & 7);
    const int mcolb = (mat >> 1) << 4;

    const int id0 = tid, id1 = tid + 256;

    float acc[4][4][4];
    #pragma unroll
    for (int i = 0; i < 4; i++)
        #pragma unroll
        for (int j = 0; j < 4; j++)
            #pragma unroll
            for (int q = 0; q < 4; q++) acc[i][j][q] = 0.f;

    auto issue_load = [&](int t) {
        const int stage = t & (STAGES - 1);
        const int pass  = ZSPLIT ? zpass : (t / NTK);
        const int k0    = (ZSPLIT ? t : (t % NTK)) * BK;
        const __nv_bfloat16* Ag = Aptr[pass] + (size_t)m0 * D_DIM + k0;
        const __nv_bfloat16* Bg = Bptr[pass] + (size_t)n0 * D_DIM + k0;
        const uint32_t bufA = sbase + stage * STAGE_B;
        const uint32_t bufB = bufA + 10240;
        {
            const int r = id0 >> 2, c = id0 & 3;
            cp_async16(bufA + r * 80 + c * 16, Ag + (size_t)r * D_DIM + c * 8);
            cp_async16(bufB + r * 80 + c * 16, Bg + (size_t)r * D_DIM + c * 8);
        }
        {
            const int r = id1 >> 2, c = id1 & 3;
            cp_async16(bufA + r * 80 + c * 16, Ag + (size_t)r * D_DIM + c * 8);
            cp_async16(bufB + r * 80 + c * 16, Bg + (size_t)r * D_DIM + c * 8);
        }
    };

    // prologue: stages 0..2 in flight
    #pragma unroll
    for (int t = 0; t < STAGES - 1; t++) {
        issue_load(t);
        asm volatile("cp.async.commit_group;" ::: "memory");
    }

    for (int t = 0; t < T; t++) {
        asm volatile("cp.async.wait_group %0;" :: "n"(STAGES - 2) : "memory");
        __syncthreads();

        if (t + STAGES - 1 < T) issue_load(t + STAGES - 1);
        asm volatile("cp.async.commit_group;" ::: "memory");

        const uint32_t bufA = sbase + (t & (STAGES - 1)) * STAGE_B;
        const uint32_t bufB = bufA + 10240;

        #pragma unroll
        for (int kk = 0; kk < 2; kk++) {          // two k16 steps
            uint32_t a[4][4];
            uint32_t b[4][2];
            #pragma unroll
            for (int mi = 0; mi < 4; mi++) {
                uint32_t addr = bufA +
                    (uint32_t)(wm * 64 + mi * 16 + mrow) * 80 + mcolb + kk * 32;
                ldmatrix_x4(a[mi], addr);
            }
            #pragma unroll
            for (int nj = 0; nj < 2; nj++) {
                uint32_t r[4];
                uint32_t addr = bufB +
                    (uint32_t)(wn * 32 + nj * 16 + mrow) * 80 + mcolb + kk * 32;
                ldmatrix_x4(r, addr);
                b[nj * 2][0]     = r[0]; b[nj * 2][1]     = r[2];
                b[nj * 2 + 1][0] = r[1]; b[nj * 2 + 1][1] = r[3];
            }
            #pragma unroll
            for (int mi = 0; mi < 4; mi++)
                #pragma unroll
                for (int ni = 0; ni < 4; ni++)
                    mma_bf16(acc[mi][ni], a[mi], b[ni]);
        }
        __syncthreads();
    }

    // ---- epilogue ----
    const int trow = lid >> 2;
    const int tcol = (lid & 3) * 2;
    #pragma unroll
    for (int mi = 0; mi < 4; mi++) {
        const int row = m0 + wm * 64 + mi * 16 + trow;
        #pragma unroll
        for (int ni = 0; ni < 4; ni++) {
            const int col = n0 + wn * 32 + ni * 8 + tcol;
            float b0 = 0.f, b1 = 0.f;
            if (!ZSPLIT && use_bias) { b0 = bias[col]; b1 = bias[col + 1]; }
            float2 v0 = {acc[mi][ni][0] + b0, acc[mi][ni][1] + b1};
            float2 v1 = {acc[mi][ni][2] + b0, acc[mi][ni][3] + b1};
            *reinterpret_cast<float2*>(&C[(size_t)row * D_DIM + col]) = v0;
            *reinterpret_cast<float2*>(&C[(size_t)(row + 8) * D_DIM + col]) = v1;
        }
    }
}

// ------------------------- host launcher -------------------------
extern "C" void kernel_launch(void* const* d_in, const int* in_sizes, int n_in,
                              void* d_out, int out_size) {
    // 0 query, 1 key, 2 value, 3 mask, 4 Wq, 5 bq, 6 Wk, 7 bk, 8 Wv, 9 bv, 10 Wo, 11 bo
    const float* value = (const float*)d_in[2];
    const float* Wv    = (const float*)d_in[8];
    const float* bv    = (const float*)d_in[9];
    const float* Wo    = (const float*)d_in[10];
    const float* bo    = (const float*)d_in[11];
    float* out = (float*)d_out;

    void *pW0, *pW1, *pW2, *pbias, *pVhi, *pVlo, *pAohi, *pAolo,
         *pBvhi, *pBvlo, *pWhi, *pWlo;
    cudaGetSymbolAddress(&pW0, g_W0);
    cudaGetSymbolAddress(&pW1, g_W1);
    cudaGetSymbolAddress(&pW2, g_W2);
    cudaGetSymbolAddress(&pbias, g_bias);
    cudaGetSymbolAddress(&pVhi, g_Vhi);
    cudaGetSymbolAddress(&pVlo, g_Vlo);
    cudaGetSymbolAddress(&pAohi, g_Aohi);
    cudaGetSymbolAddress(&pAolo, g_Aolo);
    cudaGetSymbolAddress(&pBvhi, g_Bvhi);
    cudaGetSymbolAddress(&pBvlo, g_Bvlo);
    cudaGetSymbolAddress(&pWhi, g_Whi);
    cudaGetSymbolAddress(&pWlo, g_Wlo);

    cudaFuncSetAttribute(gemm_nt_split<true>,
                         cudaFuncAttributeMaxDynamicSharedMemorySize, SMEM_SZ);
    cudaFuncSetAttribute(gemm_nt_split<false>,
                         cudaFuncAttributeMaxDynamicSharedMemorySize, SMEM_SZ);

    // 1) conversions
    {
        int n4 = (D_DIM * D_DIM) / 4;
        split_bf16_v4<<<(n4 + 255) / 256, 256>>>((const float4*)Wo,
                                                 (uint32_t*)pAohi, (uint32_t*)pAolo, n4);
    }
    {
        dim3 blk(32, 8), grd(D_DIM / 32, D_DIM / 32);
        transpose_split<<<grd, blk>>>(Wv, (__nv_bfloat16*)pBvhi, (__nv_bfloat16*)pBvlo);
    }
    {
        int n4 = (ROWS * D_DIM) / 4;
        split_bf16_v4<<<(n4 + 255) / 256, 256>>>((const float4*)value,
                                                 (uint32_t*)pVhi, (uint32_t*)pVlo, n4);
    }
    fuse_bias<<<D_DIM / 16, 512>>>(Wo, bv, bo);

    // 2) W partials: pass z of Wo @ Wv^T-form (grid.z = 3, independent CTAs)
    {
        dim3 grid(D_DIM / 128, D_DIM / 128, 3);
        gemm_nt_split<true><<<grid, 256, SMEM_SZ>>>(
            (const __nv_bfloat16*)pAohi, (const __nv_bfloat16*)pAolo,
            (const __nv_bfloat16*)pBvhi, (const __nv_bfloat16*)pBvlo,
            (float*)pW0, (size_t)D_DIM * D_DIM, nullptr, 0);
    }

    // 3) W = W0+W1+W2, split into hi/lo
    {
        int n4 = (D_DIM * D_DIM) / 4;
        sum_split_v4<<<(n4 + 255) / 256, 256>>>(
            (const float4*)pW0, (const float4*)pW1, (const float4*)pW2,
            (uint32_t*)pWhi, (uint32_t*)pWlo, n4);
    }

    // 4) out = value @ W^T + bias (3 passes in-CTA, M=4096)
    {
        dim3 grid(D_DIM / 128, ROWS / 128, 1);
        gemm_nt_split<false><<<grid, 256, SMEM_SZ>>>(
            (const __nv_bfloat16*)pVhi, (const __nv_bfloat16*)pVlo,
            (const __nv_bfloat16*)pWhi, (const __nv_bfloat16*)pWlo,
            out, 0, (const float*)pbias, 1);
    }
}

// round 6
// speedup vs baseline: 4.6049x; 1.4855x over previous
#include <cuda_runtime.h>
#include <cuda_fp16.h>
#include <cstdint>
#include <cstddef>

#define D_DIM 1024
#define ROWS  4096   // B*S

// ------------------------- device scratch -------------------------
__device__ __half g_Vh  [ROWS * D_DIM];     // fp16(value)
__device__ __half g_Aohi[D_DIM * D_DIM];    // Wo split hi  [m][k]
__device__ __half g_Aolo[D_DIM * D_DIM];    // Wo split lo
__device__ __half g_Bvhi[D_DIM * D_DIM];    // Wv^T split hi [n][k]
__device__ __half g_Bvlo[D_DIM * D_DIM];
__device__ __half g_Whi [D_DIM * D_DIM];    // W = Wo@Wv split hi [n][k]
__device__ __half g_Wlo [D_DIM * D_DIM];
__device__ float  g_bias[D_DIM];            // Wo@bv + bo

// ------------------------- helpers -------------------------
__device__ __forceinline__ uint32_t smem_u32(const void* p) {
    uint32_t a;
    asm("{ .reg .u64 t; cvta.to.shared.u64 t, %1; cvt.u32.u64 %0, t; }"
        : "=r"(a) : "l"(p));
    return a;
}

__device__ __forceinline__ void ldmatrix_x4(uint32_t* r, uint32_t addr) {
    asm volatile("ldmatrix.sync.aligned.m8n8.x4.shared.b16 {%0,%1,%2,%3}, [%4];"
                 : "=r"(r[0]), "=r"(r[1]), "=r"(r[2]), "=r"(r[3]) : "r"(addr));
}

__device__ __forceinline__ void mma_f16(float* d, const uint32_t* a,
                                        const uint32_t* b) {
    asm volatile(
        "mma.sync.aligned.m16n8k16.row.col.f32.f16.f16.f32 "
        "{%0,%1,%2,%3}, {%4,%5,%6,%7}, {%8,%9}, {%0,%1,%2,%3};"
        : "+f"(d[0]), "+f"(d[1]), "+f"(d[2]), "+f"(d[3])
        : "r"(a[0]), "r"(a[1]), "r"(a[2]), "r"(a[3]), "r"(b[0]), "r"(b[1]));
}

__device__ __forceinline__ void cp_async16(uint32_t dst, const void* src) {
    asm volatile("cp.async.cg.shared.global [%0], [%1], 16;"
                 :: "r"(dst), "l"(src) : "memory");
}

// ------------------------- conversion kernels -------------------------
__global__ void f32_to_f16_v4(const float4* __restrict__ in,
                              uint32_t* __restrict__ out, int n4) {
    int i = blockIdx.x * blockDim.x + threadIdx.x;
    if (i >= n4) return;
    float4 x = in[i];
    __half2 h0(__float2half(x.x), __float2half(x.y));
    __half2 h1(__float2half(x.z), __float2half(x.w));
    out[2 * i]     = *reinterpret_cast<uint32_t*>(&h0);
    out[2 * i + 1] = *reinterpret_cast<uint32_t*>(&h1);
}

__global__ void split_f16_v4(const float4* __restrict__ in,
                             uint32_t* __restrict__ hi,
                             uint32_t* __restrict__ lo, int n4) {
    int i = blockIdx.x * blockDim.x + threadIdx.x;
    if (i >= n4) return;
    float4 x = in[i];
    __half a0 = __float2half(x.x), a1 = __float2half(x.y);
    __half a2 = __float2half(x.z), a3 = __float2half(x.w);
    __half2 h0(a0, a1), h1(a2, a3);
    __half2 l0(__float2half(x.x - __half2float(a0)),
               __float2half(x.y - __half2float(a1)));
    __half2 l1(__float2half(x.z - __half2float(a2)),
               __float2half(x.w - __half2float(a3)));
    hi[2 * i]     = *reinterpret_cast<uint32_t*>(&h0);
    hi[2 * i + 1] = *reinterpret_cast<uint32_t*>(&h1);
    lo[2 * i]     = *reinterpret_cast<uint32_t*>(&l0);
    lo[2 * i + 1] = *reinterpret_cast<uint32_t*>(&l1);
}

// Wv[k][n] -> out_hi/lo[n][k]  (transpose + fp16 split)
__global__ void transpose_split_f16(const float* __restrict__ in,
                                    __half* __restrict__ hi,
                                    __half* __restrict__ lo) {
    __shared__ float tile[32][33];
    int x = blockIdx.x * 32 + threadIdx.x;
    int y = blockIdx.y * 32;
    #pragma unroll
    for (int j = threadIdx.y; j < 32; j += 8)
        tile[j][threadIdx.x] = in[(size_t)(y + j) * D_DIM + x];
    __syncthreads();
    int ox = blockIdx.y * 32 + threadIdx.x;
    int oyb = blockIdx.x * 32;
    #pragma unroll
    for (int j = threadIdx.y; j < 32; j += 8) {
        float v = tile[threadIdx.x][j];
        __half h = __float2half(v);
        size_t o = (size_t)(oyb + j) * D_DIM + ox;
        hi[o] = h;
        lo[o] = __float2half(v - __half2float(h));
    }
}

// g_bias[o] = bo[o] + sum_k Wo[o][k] * bv[k]   (warp per row, float4 loads)
__global__ void fuse_bias(const float* __restrict__ Wo,
                          const float* __restrict__ bv,
                          const float* __restrict__ bo) {
    const int wid = threadIdx.x >> 5;
    const int lid = threadIdx.x & 31;
    const int row = blockIdx.x * 4 + wid;
    const float4* r4 = (const float4*)(Wo + (size_t)row * D_DIM);
    const float4* b4 = (const float4*)bv;
    float s = 0.f;
    #pragma unroll
    for (int i = 0; i < 8; i++) {
        float4 a = r4[lid + i * 32];
        float4 b = b4[lid + i * 32];
        s += a.x * b.x + a.y * b.y + a.z * b.z + a.w * b.w;
    }
    #pragma unroll
    for (int o = 16; o > 0; o >>= 1)
        s += __shfl_down_sync(0xFFFFFFFFu, s, o);
    if (lid == 0) g_bias[row] = s + bo[row];
}

// ------------------------- merged multi-term NT GEMM (mma.sync fp16) ------
// C[m][n] = sum_k A0[m,k]*B0[n,k] + A0*B1 (+ A1*B0 if TERMS==3), fp32 accum,
// all terms fused in ONE k-loop (same accumulators).
// Square CTA tile BT x BT; warp tile WM x 32; BK=32; 3-stage cp.async.
// SPLITOUT: epilogue writes fp16 hi/lo of result instead of fp32 C (+bias).
template <int BT, int WM, int TERMS, bool SPLITOUT>
__global__ void __launch_bounds__((BT / WM) * (BT / 32) * 32, 2)
gemm_nt(const __half* __restrict__ A0, const __half* __restrict__ A1,
        const __half* __restrict__ B0, const __half* __restrict__ B1,
        float* __restrict__ C, __half* __restrict__ Chi,
        __half* __restrict__ Clo, const float* __restrict__ bias) {
    constexpr int NWX     = BT / 32;                 // warps along N
    constexpr int MI      = WM / 16;
    constexpr int NTILES  = (TERMS == 3) ? 4 : 3;    // A0[,A1],B0,B1
    constexpr int TPB     = BT * 80;                 // tile pitch bytes (pad 40 h)
    constexpr int STAGE_B = NTILES * TPB;
    constexpr int NT      = (BT / WM) * NWX * 32;
    constexpr int CHK     = (BT * 4) / NT;           // 16B chunks per thread/tile
    constexpr int T       = D_DIM / 32;              // 32 k-tiles
    constexpr int STAGES  = 3;

    extern __shared__ __align__(128) char smem[];
    const uint32_t sbase = smem_u32(smem);

    const int tid = threadIdx.x;
    const int wid = tid >> 5;
    const int lid = tid & 31;
    const int wm  = wid / NWX;
    const int wn  = wid % NWX;
    const int m0  = blockIdx.y * BT;
    const int n0  = blockIdx.x * BT;

    const __half* gp[NTILES];
    gp[0] = A0 + (size_t)m0 * D_DIM;
    if (TERMS == 3) gp[1] = A1 + (size_t)m0 * D_DIM;
    gp[NTILES - 2] = B0 + (size_t)n0 * D_DIM;
    gp[NTILES - 1] = B1 + (size_t)n0 * D_DIM;

    // ldmatrix lane geometry
    const int mat   = lid >> 3;
    const int mrow  = ((mat & 1) << 3) + (lid & 7);
    const int mcolb = (mat >> 1) << 4;

    float acc[MI][4][4];
    #pragma unroll
    for (int i = 0; i < MI; i++)
        #pragma unroll
        for (int j = 0; j < 4; j++)
            #pragma unroll
            for (int q = 0; q < 4; q++) acc[i][j][q] = 0.f;

    auto issue = [&](int t) {
        const uint32_t sb = sbase + (t % STAGES) * STAGE_B;
        const int k0 = t * 32;
        #pragma unroll
        for (int ti = 0; ti < NTILES; ti++) {
            #pragma unroll
            for (int i = 0; i < CHK; i++) {
                const int c = tid + i * NT;
                const int r = c >> 2, cc = c & 3;
                cp_async16(sb + ti * TPB + r * 80 + cc * 16,
                           gp[ti] + (size_t)r * D_DIM + k0 + cc * 8);
            }
        }
    };

    #pragma unroll
    for (int t = 0; t < STAGES - 1; t++) {
        issue(t);
        asm volatile("cp.async.commit_group;" ::: "memory");
    }

    for (int t = 0; t < T; t++) {
        asm volatile("cp.async.wait_group %0;" :: "n"(STAGES - 2) : "memory");
        __syncthreads();

        if (t + STAGES - 1 < T) issue(t + STAGES - 1);
        asm volatile("cp.async.commit_group;" ::: "memory");

        const uint32_t sb   = sbase + (t % STAGES) * STAGE_B;
        const uint32_t bA0  = sb;
        const uint32_t bA1  = sb + TPB;                       // valid iff TERMS==3
        const uint32_t bB0  = sb + (NTILES - 2) * TPB;
        const uint32_t bB1  = sb + (NTILES - 1) * TPB;

        #pragma unroll
        for (int kk = 0; kk < 2; kk++) {
            uint32_t a0[MI][4], a1[MI][4];
            uint32_t b0[4][2], b1[4][2];
            #pragma unroll
            for (int mi = 0; mi < MI; mi++) {
                uint32_t roff = (uint32_t)(wm * WM + mi * 16 + mrow) * 80 +
                                mcolb + kk * 32;
                ldmatrix_x4(a0[mi], bA0 + roff);
                if (TERMS == 3) ldmatrix_x4(a1[mi], bA1 + roff);
            }
            #pragma unroll
            for (int nj = 0; nj < 2; nj++) {
                uint32_t roff = (uint32_t)(wn * 32 + nj * 16 + mrow) * 80 +
                                mcolb + kk * 32;
                uint32_t r[4];
                ldmatrix_x4(r, bB0 + roff);
                b0[nj * 2][0]     = r[0]; b0[nj * 2][1]     = r[2];
                b0[nj * 2 + 1][0] = r[1]; b0[nj * 2 + 1][1] = r[3];
                ldmatrix_x4(r, bB1 + roff);
                b1[nj * 2][0]     = r[0]; b1[nj * 2][1]     = r[2];
                b1[nj * 2 + 1][0] = r[1]; b1[nj * 2 + 1][1] = r[3];
            }
            #pragma unroll
            for (int mi = 0; mi < MI; mi++)
                #pragma unroll
                for (int ni = 0; ni < 4; ni++) {
                    mma_f16(acc[mi][ni], a0[mi], b0[ni]);
                    mma_f16(acc[mi][ni], a0[mi], b1[ni]);
                    if (TERMS == 3) mma_f16(acc[mi][ni], a1[mi], b0[ni]);
                }
        }
        __syncthreads();
    }

    // ---- epilogue ----
    const int trow = lid >> 2;
    const int tcol = (lid & 3) * 2;
    #pragma unroll
    for (int mi = 0; mi < MI; mi++) {
        const int row = m0 + wm * WM + mi * 16 + trow;
        #pragma unroll
        for (int ni = 0; ni < 4; ni++) {
            const int col = n0 + wn * 32 + ni * 8 + tcol;
            if (SPLITOUT) {
                #pragma unroll
                for (int h = 0; h < 2; h++) {
                    const int rr = row + h * 8;
                    float x0 = acc[mi][ni][h * 2 + 0];
                    float x1 = acc[mi][ni][h * 2 + 1];
                    __half h0 = __float2half(x0), h1 = __float2half(x1);
                    __half2 hv(h0, h1);
                    __half2 lv(__float2half(x0 - __half2float(h0)),
                               __float2half(x1 - __half2float(h1)));
                    *reinterpret_cast<__half2*>(&Chi[(size_t)rr * D_DIM + col]) = hv;
                    *reinterpret_cast<__half2*>(&Clo[(size_t)rr * D_DIM + col]) = lv;
                }
            } else {
                float b0v = bias[col], b1v = bias[col + 1];
                float2 v0 = {acc[mi][ni][0] + b0v, acc[mi][ni][1] + b1v};
                float2 v1 = {acc[mi][ni][2] + b0v, acc[mi][ni][3] + b1v};
                *reinterpret_cast<float2*>(&C[(size_t)row * D_DIM + col]) = v0;
                *reinterpret_cast<float2*>(&C[(size_t)(row + 8) * D_DIM + col]) = v1;
            }
        }
    }
}

// ------------------------- host launcher -------------------------
#define SMEM_G1 (3 * 4 * 64 * 80)    // 61440
#define SMEM_G2 (3 * 3 * 128 * 80)   // 92160

extern "C" void kernel_launch(void* const* d_in, const int* in_sizes, int n_in,
                              void* d_out, int out_size) {
    // 0 query, 1 key, 2 value, 3 mask, 4 Wq, 5 bq, 6 Wk, 7 bk, 8 Wv, 9 bv, 10 Wo, 11 bo
    const float* value = (const float*)d_in[2];
    const float* Wv    = (const float*)d_in[8];
    const float* bv    = (const float*)d_in[9];
    const float* Wo    = (const float*)d_in[10];
    const float* bo    = (const float*)d_in[11];
    float* out = (float*)d_out;

    void *pVh, *pAohi, *pAolo, *pBvhi, *pBvlo, *pWhi, *pWlo, *pbias;
    cudaGetSymbolAddress(&pVh, g_Vh);
    cudaGetSymbolAddress(&pAohi, g_Aohi);
    cudaGetSymbolAddress(&pAolo, g_Aolo);
    cudaGetSymbolAddress(&pBvhi, g_Bvhi);
    cudaGetSymbolAddress(&pBvlo, g_Bvlo);
    cudaGetSymbolAddress(&pWhi, g_Whi);
    cudaGetSymbolAddress(&pWlo, g_Wlo);
    cudaGetSymbolAddress(&pbias, g_bias);

    cudaFuncSetAttribute((const void*)gemm_nt<64, 32, 3, true>,
                         cudaFuncAttributeMaxDynamicSharedMemorySize, SMEM_G1);
    cudaFuncSetAttribute((const void*)gemm_nt<128, 64, 2, false>,
                         cudaFuncAttributeMaxDynamicSharedMemorySize, SMEM_G2);

    // conversions
    {
        int n4 = (D_DIM * D_DIM) / 4;
        split_f16_v4<<<n4 / 256, 256>>>((const float4*)Wo,
                                        (uint32_t*)pAohi, (uint32_t*)pAolo, n4);
    }
    {
        dim3 blk(32, 8), grd(D_DIM / 32, D_DIM / 32);
        transpose_split_f16<<<grd, blk>>>(Wv, (__half*)pBvhi, (__half*)pBvlo);
    }
    {
        int n4 = (ROWS * D_DIM) / 4;
        f32_to_f16_v4<<<n4 / 256, 256>>>((const float4*)value, (uint32_t*)pVh, n4);
    }
    fuse_bias<<<D_DIM / 4, 128>>>(Wo, bv, bo);

    // GEMM1: W = Wo @ Wv  (3-term fp16, writes Whi/Wlo directly)
    {
        dim3 grid(D_DIM / 64, D_DIM / 64);
        gemm_nt<64, 32, 3, true><<<grid, 128, SMEM_G1>>>(
            (const __half*)pAohi, (const __half*)pAolo,
            (const __half*)pBvhi, (const __half*)pBvlo,
            nullptr, (__half*)pWhi, (__half*)pWlo, nullptr);
    }

    // GEMM2: out = Vh @ (Whi + Wlo)^T + bias  (2-term fp16, one k-loop)
    {
        dim3 grid(D_DIM / 128, ROWS / 128);
        gemm_nt<128, 64, 2, false><<<grid, 256, SMEM_G2>>>(
            (const __half*)pVh, nullptr,
            (const __half*)pWhi, (const __half*)pWlo,
            out, nullptr, nullptr, (const float*)pbias);
    }
}

// round 7
// speedup vs baseline: 6.1799x; 1.3420x over previous
#include <cuda_runtime.h>
#include <cuda_fp16.h>
#include <cstdint>
#include <cstddef>

#define D_DIM 1024
#define ROWS  4096   // B*S

// ------------------------- device scratch -------------------------
__device__ __half g_Vh  [ROWS * D_DIM];     // fp16(value)
__device__ __half g_Aohi[D_DIM * D_DIM];    // Wo split hi  [m][k]
__device__ __half g_Aolo[D_DIM * D_DIM];    // Wo split lo
__device__ __half g_Bvhi[D_DIM * D_DIM];    // Wv^T split hi [n][k]
__device__ __half g_Bvlo[D_DIM * D_DIM];
__device__ __half g_Whi [D_DIM * D_DIM];    // fp16(W = Wo@Wv) [n][k]
__device__ float  g_bias[D_DIM];            // Wo@bv + bo

// ------------------------- helpers -------------------------
__device__ __forceinline__ uint32_t smem_u32(const void* p) {
    uint32_t a;
    asm("{ .reg .u64 t; cvta.to.shared.u64 t, %1; cvt.u32.u64 %0, t; }"
        : "=r"(a) : "l"(p));
    return a;
}

__device__ __forceinline__ void ldmatrix_x4(uint32_t* r, uint32_t addr) {
    asm volatile("ldmatrix.sync.aligned.m8n8.x4.shared.b16 {%0,%1,%2,%3}, [%4];"
                 : "=r"(r[0]), "=r"(r[1]), "=r"(r[2]), "=r"(r[3]) : "r"(addr));
}

__device__ __forceinline__ void mma_f16(float* d, const uint32_t* a,
                                        const uint32_t* b) {
    asm volatile(
        "mma.sync.aligned.m16n8k16.row.col.f32.f16.f16.f32 "
        "{%0,%1,%2,%3}, {%4,%5,%6,%7}, {%8,%9}, {%0,%1,%2,%3};"
        : "+f"(d[0]), "+f"(d[1]), "+f"(d[2]), "+f"(d[3])
        : "r"(a[0]), "r"(a[1]), "r"(a[2]), "r"(a[3]), "r"(b[0]), "r"(b[1]));
}

__device__ __forceinline__ void cp_async16(uint32_t dst, const void* src) {
    asm volatile("cp.async.cg.shared.global [%0], [%1], 16;"
                 :: "r"(dst), "l"(src) : "memory");
}

// ------------------------- conversion kernels -------------------------
__global__ void f32_to_f16_v4(const float4* __restrict__ in,
                              uint32_t* __restrict__ out, int n4) {
    int i = blockIdx.x * blockDim.x + threadIdx.x;
    if (i >= n4) return;
    float4 x = in[i];
    __half2 h0(__float2half(x.x), __float2half(x.y));
    __half2 h1(__float2half(x.z), __float2half(x.w));
    out[2 * i]     = *reinterpret_cast<uint32_t*>(&h0);
    out[2 * i + 1] = *reinterpret_cast<uint32_t*>(&h1);
}

__global__ void split_f16_v4(const float4* __restrict__ in,
                             uint32_t* __restrict__ hi,
                             uint32_t* __restrict__ lo, int n4) {
    int i = blockIdx.x * blockDim.x + threadIdx.x;
    if (i >= n4) return;
    float4 x = in[i];
    __half a0 = __float2half(x.x), a1 = __float2half(x.y);
    __half a2 = __float2half(x.z), a3 = __float2half(x.w);
    __half2 h0(a0, a1), h1(a2, a3);
    __half2 l0(__float2half(x.x - __half2float(a0)),
               __float2half(x.y - __half2float(a1)));
    __half2 l1(__float2half(x.z - __half2float(a2)),
               __float2half(x.w - __half2float(a3)));
    hi[2 * i]     = *reinterpret_cast<uint32_t*>(&h0);
    hi[2 * i + 1] = *reinterpret_cast<uint32_t*>(&h1);
    lo[2 * i]     = *reinterpret_cast<uint32_t*>(&l0);
    lo[2 * i + 1] = *reinterpret_cast<uint32_t*>(&l1);
}

// Wv[k][n] -> out_hi/lo[n][k]  (transpose + fp16 split)
__global__ void transpose_split_f16(const float* __restrict__ in,
                                    __half* __restrict__ hi,
                                    __half* __restrict__ lo) {
    __shared__ float tile[32][33];
    int x = blockIdx.x * 32 + threadIdx.x;
    int y = blockIdx.y * 32;
    #pragma unroll
    for (int j = threadIdx.y; j < 32; j += 8)
        tile[j][threadIdx.x] = in[(size_t)(y + j) * D_DIM + x];
    __syncthreads();
    int ox = blockIdx.y * 32 + threadIdx.x;
    int oyb = blockIdx.x * 32;
    #pragma unroll
    for (int j = threadIdx.y; j < 32; j += 8) {
        float v = tile[threadIdx.x][j];
        __half h = __float2half(v);
        size_t o = (size_t)(oyb + j) * D_DIM + ox;
        hi[o] = h;
        lo[o] = __float2half(v - __half2float(h));
    }
}

// g_bias[o] = bo[o] + sum_k Wo[o][k] * bv[k]   (warp per row, float4 loads)
__global__ void fuse_bias(const float* __restrict__ Wo,
                          const float* __restrict__ bv,
                          const float* __restrict__ bo) {
    const int wid = threadIdx.x >> 5;
    const int lid = threadIdx.x & 31;
    const int row = blockIdx.x * 4 + wid;
    const float4* r4 = (const float4*)(Wo + (size_t)row * D_DIM);
    const float4* b4 = (const float4*)bv;
    float s = 0.f;
    #pragma unroll
    for (int i = 0; i < 8; i++) {
        float4 a = r4[lid + i * 32];
        float4 b = b4[lid + i * 32];
        s += a.x * b.x + a.y * b.y + a.z * b.z + a.w * b.w;
    }
    #pragma unroll
    for (int o = 16; o > 0; o >>= 1)
        s += __shfl_down_sync(0xFFFFFFFFu, s, o);
    if (lid == 0) g_bias[row] = s + bo[row];
}

// ------------------------- merged multi-term NT GEMM (mma.sync fp16) ------
// TERMS==1: C = A0 B0^T
// TERMS==3: C = A0 B0^T + A0 B1^T + A1 B0^T    (all in one k-loop, fp32 accum)
// Square CTA tile BT x BT; warp tile WM x 32; BK=32; STAGES-deep cp.async.
// SPLITOUT: epilogue writes fp16(result) to Chi instead of fp32 C (+bias).
template <int BT, int WM, int TERMS, int STAGES, bool SPLITOUT>
__global__ void __launch_bounds__((BT / WM) * (BT / 32) * 32, 2)
gemm_nt(const __half* __restrict__ A0, const __half* __restrict__ A1,
        const __half* __restrict__ B0, const __half* __restrict__ B1,
        float* __restrict__ C, __half* __restrict__ Chi,
        const float* __restrict__ bias) {
    constexpr int NWX     = BT / 32;                 // warps along N
    constexpr int MI      = WM / 16;
    constexpr int NTILES  = (TERMS == 3) ? 4 : 2;    // A0[,A1],B0[,B1]
    constexpr int TPB     = BT * 80;                 // tile pitch bytes (pad 40 h)
    constexpr int STAGE_B = NTILES * TPB;
    constexpr int NT      = (BT / WM) * NWX * 32;
    constexpr int CHK     = (BT * 4) / NT;           // 16B chunks per thread/tile
    constexpr int T       = D_DIM / 32;              // 32 k-tiles

    extern __shared__ __align__(128) char smem[];
    const uint32_t sbase = smem_u32(smem);

    const int tid = threadIdx.x;
    const int wid = tid >> 5;
    const int lid = tid & 31;
    const int wm  = wid / NWX;
    const int wn  = wid % NWX;
    const int m0  = blockIdx.y * BT;
    const int n0  = blockIdx.x * BT;

    const __half* gp[NTILES];
    gp[0] = A0 + (size_t)m0 * D_DIM;
    if (TERMS == 3) {
        gp[1] = A1 + (size_t)m0 * D_DIM;
        gp[2] = B0 + (size_t)n0 * D_DIM;
        gp[3] = B1 + (size_t)n0 * D_DIM;
    } else {
        gp[1] = B0 + (size_t)n0 * D_DIM;
    }

    // ldmatrix lane geometry
    const int mat   = lid >> 3;
    const int mrow  = ((mat & 1) << 3) + (lid & 7);
    const int mcolb = (mat >> 1) << 4;

    float acc[MI][4][4];
    #pragma unroll
    for (int i = 0; i < MI; i++)
        #pragma unroll
        for (int j = 0; j < 4; j++)
            #pragma unroll
            for (int q = 0; q < 4; q++) acc[i][j][q] = 0.f;

    auto issue = [&](int t) {
        const uint32_t sb = sbase + (t % STAGES) * STAGE_B;
        const int k0 = t * 32;
        #pragma unroll
        for (int ti = 0; ti < NTILES; ti++) {
            #pragma unroll
            for (int i = 0; i < CHK; i++) {
                const int c = tid + i * NT;
                const int r = c >> 2, cc = c & 3;
                cp_async16(sb + ti * TPB + r * 80 + cc * 16,
                           gp[ti] + (size_t)r * D_DIM + k0 + cc * 8);
            }
        }
    };

    #pragma unroll
    for (int t = 0; t < STAGES - 1; t++) {
        issue(t);
        asm volatile("cp.async.commit_group;" ::: "memory");
    }

    for (int t = 0; t < T; t++) {
        asm volatile("cp.async.wait_group %0;" :: "n"(STAGES - 2) : "memory");
        __syncthreads();

        if (t + STAGES - 1 < T) issue(t + STAGES - 1);
        asm volatile("cp.async.commit_group;" ::: "memory");

        const uint32_t sb  = sbase + (t % STAGES) * STAGE_B;
        const uint32_t bA0 = sb;
        const uint32_t bA1 = sb + TPB;                    // TERMS==3 only
        const uint32_t bB0 = sb + (NTILES - (TERMS == 3 ? 2 : 1)) * TPB;
        const uint32_t bB1 = sb + (NTILES - 1) * TPB;     // TERMS==3 only

        #pragma unroll
        for (int kk = 0; kk < 2; kk++) {
            uint32_t a0[MI][4], a1[MI][4];
            uint32_t b0[4][2], b1[4][2];
            #pragma unroll
            for (int mi = 0; mi < MI; mi++) {
                uint32_t roff = (uint32_t)(wm * WM + mi * 16 + mrow) * 80 +
                                mcolb + kk * 32;
                ldmatrix_x4(a0[mi], bA0 + roff);
                if (TERMS == 3) ldmatrix_x4(a1[mi], bA1 + roff);
            }
            #pragma unroll
            for (int nj = 0; nj < 2; nj++) {
                uint32_t roff = (uint32_t)(wn * 32 + nj * 16 + mrow) * 80 +
                                mcolb + kk * 32;
                uint32_t r[4];
                ldmatrix_x4(r, bB0 + roff);
                b0[nj * 2][0]     = r[0]; b0[nj * 2][1]     = r[2];
                b0[nj * 2 + 1][0] = r[1]; b0[nj * 2 + 1][1] = r[3];
                if (TERMS == 3) {
                    ldmatrix_x4(r, bB1 + roff);
                    b1[nj * 2][0]     = r[0]; b1[nj * 2][1]     = r[2];
                    b1[nj * 2 + 1][0] = r[1]; b1[nj * 2 + 1][1] = r[3];
                }
            }
            #pragma unroll
            for (int mi = 0; mi < MI; mi++)
                #pragma unroll
                for (int ni = 0; ni < 4; ni++) {
                    mma_f16(acc[mi][ni], a0[mi], b0[ni]);
                    if (TERMS == 3) {
                        mma_f16(acc[mi][ni], a0[mi], b1[ni]);
                        mma_f16(acc[mi][ni], a1[mi], b0[ni]);
                    }
                }
        }
        __syncthreads();
    }

    // ---- epilogue ----
    const int trow = lid >> 2;
    const int tcol = (lid & 3) * 2;
    #pragma unroll
    for (int mi = 0; mi < MI; mi++) {
        const int row = m0 + wm * WM + mi * 16 + trow;
        #pragma unroll
        for (int ni = 0; ni < 4; ni++) {
            const int col = n0 + wn * 32 + ni * 8 + tcol;
            if (SPLITOUT) {
                #pragma unroll
                for (int h = 0; h < 2; h++) {
                    const int rr = row + h * 8;
                    __half2 hv(__float2half(acc[mi][ni][h * 2 + 0]),
                               __float2half(acc[mi][ni][h * 2 + 1]));
                    *reinterpret_cast<__half2*>(&Chi[(size_t)rr * D_DIM + col]) = hv;
                }
            } else {
                float b0v = bias[col], b1v = bias[col + 1];
                float2 v0 = {acc[mi][ni][0] + b0v, acc[mi][ni][1] + b1v};
                float2 v1 = {acc[mi][ni][2] + b0v, acc[mi][ni][3] + b1v};
                *reinterpret_cast<float2*>(&C[(size_t)row * D_DIM + col]) = v0;
                *reinterpret_cast<float2*>(&C[(size_t)(row + 8) * D_DIM + col]) = v1;
            }
        }
    }
}

// ------------------------- host launcher -------------------------
#define SMEM_G1 (3 * 4 * 64 * 80)    // 61440  (3 stages, 4 tiles, BT=64)
#define SMEM_G2 (4 * 2 * 128 * 80)   // 81920  (4 stages, 2 tiles, BT=128)

extern "C" void kernel_launch(void* const* d_in, const int* in_sizes, int n_in,
                              void* d_out, int out_size) {
    // 0 query, 1 key, 2 value, 3 mask, 4 Wq, 5 bq, 6 Wk, 7 bk, 8 Wv, 9 bv, 10 Wo, 11 bo
    const float* value = (const float*)d_in[2];
    const float* Wv    = (const float*)d_in[8];
    const float* bv    = (const float*)d_in[9];
    const float* Wo    = (const float*)d_in[10];
    const float* bo    = (const float*)d_in[11];
    float* out = (float*)d_out;

    void *pVh, *pAohi, *pAolo, *pBvhi, *pBvlo, *pWhi, *pbias;
    cudaGetSymbolAddress(&pVh, g_Vh);
    cudaGetSymbolAddress(&pAohi, g_Aohi);
    cudaGetSymbolAddress(&pAolo, g_Aolo);
    cudaGetSymbolAddress(&pBvhi, g_Bvhi);
    cudaGetSymbolAddress(&pBvlo, g_Bvlo);
    cudaGetSymbolAddress(&pWhi, g_Whi);
    cudaGetSymbolAddress(&pbias, g_bias);

    cudaFuncSetAttribute((const void*)gemm_nt<64, 32, 3, 3, true>,
                         cudaFuncAttributeMaxDynamicSharedMemorySize, SMEM_G1);
    cudaFuncSetAttribute((const void*)gemm_nt<128, 64, 1, 4, false>,
                         cudaFuncAttributeMaxDynamicSharedMemorySize, SMEM_G2);

    // conversions
    {
        int n4 = (D_DIM * D_DIM) / 4;
        split_f16_v4<<<n4 / 256, 256>>>((const float4*)Wo,
                                        (uint32_t*)pAohi, (uint32_t*)pAolo, n4);
    }
    {
        dim3 blk(32, 8), grd(D_DIM / 32, D_DIM / 32);
        transpose_split_f16<<<grd, blk>>>(Wv, (__half*)pBvhi, (__half*)pBvlo);
    }
    {
        int n4 = (ROWS * D_DIM) / 4;
        f32_to_f16_v4<<<n4 / 256, 256>>>((const float4*)value, (uint32_t*)pVh, n4);
    }
    fuse_bias<<<D_DIM / 4, 128>>>(Wo, bv, bo);

    // GEMM1: W = Wo @ Wv  (3-term fp16, fp32 accum, writes fp16 Whi)
    {
        dim3 grid(D_DIM / 64, D_DIM / 64);
        gemm_nt<64, 32, 3, 3, true><<<grid, 128, SMEM_G1>>>(
            (const __half*)pAohi, (const __half*)pAolo,
            (const __half*)pBvhi, (const __half*)pBvlo,
            nullptr, (__half*)pWhi, nullptr);
    }

    // GEMM2: out = Vh @ Whi^T + bias  (1-term fp16)
    {
        dim3 grid(D_DIM / 128, ROWS / 128);
        gemm_nt<128, 64, 1, 4, false><<<grid, 256, SMEM_G2>>>(
            (const __half*)pVh, nullptr,
            (const __half*)pWhi, nullptr,
            out, nullptr, (const float*)pbias);
    }
}

// round 8
// speedup vs baseline: 7.4430x; 1.2044x over previous
#include <cuda_runtime.h>
#include <cuda_fp16.h>
#include <cstdint>
#include <cstddef>

#define D_DIM 1024
#define ROWS  4096   // B*S

// ------------------------- device scratch -------------------------
__device__ __half g_Vh  [ROWS * D_DIM];     // fp16(value)
__device__ __half g_Aoh [D_DIM * D_DIM];    // fp16(Wo)      [m][k]
__device__ __half g_Bvhi[D_DIM * D_DIM];    // Wv^T split hi [n][k]
__device__ __half g_Bvlo[D_DIM * D_DIM];    // Wv^T split lo
__device__ __half g_Whi [D_DIM * D_DIM];    // fp16(W = Wo@Wv) [n][k]
__device__ float  g_bias[D_DIM];            // Wo@bv + bo

// ------------------------- helpers -------------------------
__device__ __forceinline__ uint32_t smem_u32(const void* p) {
    uint32_t a;
    asm("{ .reg .u64 t; cvta.to.shared.u64 t, %1; cvt.u32.u64 %0, t; }"
        : "=r"(a) : "l"(p));
    return a;
}

__device__ __forceinline__ void ldmatrix_x4(uint32_t* r, uint32_t addr) {
    asm volatile("ldmatrix.sync.aligned.m8n8.x4.shared.b16 {%0,%1,%2,%3}, [%4];"
                 : "=r"(r[0]), "=r"(r[1]), "=r"(r[2]), "=r"(r[3]) : "r"(addr));
}

__device__ __forceinline__ void mma_f16(float* d, const uint32_t* a,
                                        const uint32_t* b) {
    asm volatile(
        "mma.sync.aligned.m16n8k16.row.col.f32.f16.f16.f32 "
        "{%0,%1,%2,%3}, {%4,%5,%6,%7}, {%8,%9}, {%0,%1,%2,%3};"
        : "+f"(d[0]), "+f"(d[1]), "+f"(d[2]), "+f"(d[3])
        : "r"(a[0]), "r"(a[1]), "r"(a[2]), "r"(a[3]), "r"(b[0]), "r"(b[1]));
}

__device__ __forceinline__ void cp_async16(uint32_t dst, const void* src) {
    asm volatile("cp.async.cg.shared.global [%0], [%1], 16;"
                 :: "r"(dst), "l"(src) : "memory");
}

// ------------------------- conversion kernels -------------------------
__global__ void f32_to_f16_v4(const float4* __restrict__ in,
                              uint32_t* __restrict__ out, int n4) {
    int i = blockIdx.x * blockDim.x + threadIdx.x;
    if (i >= n4) return;
    float4 x = in[i];
    __half2 h0(__float2half(x.x), __float2half(x.y));
    __half2 h1(__float2half(x.z), __float2half(x.w));
    out[2 * i]     = *reinterpret_cast<uint32_t*>(&h0);
    out[2 * i + 1] = *reinterpret_cast<uint32_t*>(&h1);
}

// Wv[k][n] -> out_hi/lo[n][k]  (transpose + fp16 split)
__global__ void transpose_split_f16(const float* __restrict__ in,
                                    __half* __restrict__ hi,
                                    __half* __restrict__ lo) {
    __shared__ float tile[32][33];
    int x = blockIdx.x * 32 + threadIdx.x;
    int y = blockIdx.y * 32;
    #pragma unroll
    for (int j = threadIdx.y; j < 32; j += 8)
        tile[j][threadIdx.x] = in[(size_t)(y + j) * D_DIM + x];
    __syncthreads();
    int ox = blockIdx.y * 32 + threadIdx.x;
    int oyb = blockIdx.x * 32;
    #pragma unroll
    for (int j = threadIdx.y; j < 32; j += 8) {
        float v = tile[threadIdx.x][j];
        __half h = __float2half(v);
        size_t o = (size_t)(oyb + j) * D_DIM + ox;
        hi[o] = h;
        lo[o] = __float2half(v - __half2float(h));
    }
}

// g_bias[row] = bo[row] + sum_k Wo[row][k]*bv[k]  (block per row, 256 thr)
__global__ void fuse_bias(const float* __restrict__ Wo,
                          const float* __restrict__ bv,
                          const float* __restrict__ bo) {
    __shared__ float red[8];
    const int row = blockIdx.x;
    const int tid = threadIdx.x;
    float4 a = ((const float4*)(Wo + (size_t)row * D_DIM))[tid];
    float4 b = ((const float4*)bv)[tid];
    float s = a.x * b.x + a.y * b.y + a.z * b.z + a.w * b.w;
    #pragma unroll
    for (int o = 16; o > 0; o >>= 1)
        s += __shfl_down_sync(0xFFFFFFFFu, s, o);
    if ((tid & 31) == 0) red[tid >> 5] = s;
    __syncthreads();
    if (tid < 8) {
        s = red[tid];
        #pragma unroll
        for (int o = 4; o > 0; o >>= 1)
            s += __shfl_down_sync(0xFFu, s, o);
        if (tid == 0) g_bias[row] = s + bo[row];
    }
}

// ------------------------- merged multi-term NT GEMM (mma.sync fp16) ------
// TERMS==1: C = A0 B0^T
// TERMS==2: C = A0 B0^T + A0 B1^T          (one k-loop, shared fp32 accum)
// CTA tile BT x BT; warp tile WM x WN; BK=64; STAGES-deep cp.async.
// SPLITOUT: epilogue writes fp16(result) to Chi instead of fp32 C (+bias).
#define BKK   64
#define PITCH 144                            // 128B payload + 16B pad

template <int BT, int WM, int WN, int TERMS, int STAGES, bool SPLITOUT>
__global__ void __launch_bounds__((BT / WM) * (BT / WN) * 32, 2)
gemm_nt(const __half* __restrict__ A0,
        const __half* __restrict__ B0, const __half* __restrict__ B1,
        float* __restrict__ C, __half* __restrict__ Chi,
        const float* __restrict__ bias) {
    constexpr int NWX     = BT / WN;         // warps along N
    constexpr int MI      = WM / 16;
    constexpr int NI      = WN / 8;
    constexpr int NJ      = WN / 16;
    constexpr int NTILES  = (TERMS == 2) ? 3 : 2;   // A0, B0[, B1]
    constexpr int TPB     = BT * PITCH;
    constexpr int STAGE_B = NTILES * TPB;
    constexpr int NT      = (BT / WM) * NWX * 32;
    constexpr int CHK     = (BT * 8) / NT;   // 16B chunks / thread / tile
    constexpr int T       = D_DIM / BKK;     // 16 k-tiles

    extern __shared__ __align__(128) char smem[];
    const uint32_t sbase = smem_u32(smem);

    const int tid = threadIdx.x;
    const int wid = tid >> 5;
    const int lid = tid & 31;
    const int wm  = wid / NWX;
    const int wn  = wid % NWX;
    const int m0  = blockIdx.y * BT;
    const int n0  = blockIdx.x * BT;

    const __half* gp[NTILES];
    gp[0] = A0 + (size_t)m0 * D_DIM;
    gp[1] = B0 + (size_t)n0 * D_DIM;
    if (TERMS == 2) gp[2] = B1 + (size_t)n0 * D_DIM;

    // ldmatrix lane geometry
    const int mat   = lid >> 3;
    const int mrow  = ((mat & 1) << 3) + (lid & 7);
    const int mcolb = (mat >> 1) << 4;

    float acc[MI][NI][4];
    #pragma unroll
    for (int i = 0; i < MI; i++)
        #pragma unroll
        for (int j = 0; j < NI; j++)
            #pragma unroll
            for (int q = 0; q < 4; q++) acc[i][j][q] = 0.f;

    auto issue = [&](int t) {
        const uint32_t sb = sbase + (t % STAGES) * STAGE_B;
        const int k0 = t * BKK;
        #pragma unroll
        for (int ti = 0; ti < NTILES; ti++) {
            #pragma unroll
            for (int i = 0; i < CHK; i++) {
                const int c = tid + i * NT;
                const int r = c >> 3, cc = c & 7;
                cp_async16(sb + ti * TPB + r * PITCH + cc * 16,
                           gp[ti] + (size_t)r * D_DIM + k0 + cc * 8);
            }
        }
    };

    #pragma unroll
    for (int t = 0; t < STAGES - 1; t++) {
        issue(t);
        asm volatile("cp.async.commit_group;" ::: "memory");
    }

    for (int t = 0; t < T; t++) {
        asm volatile("cp.async.wait_group %0;" :: "n"(STAGES - 2) : "memory");
        __syncthreads();

        if (t + STAGES - 1 < T) issue(t + STAGES - 1);
        asm volatile("cp.async.commit_group;" ::: "memory");

        const uint32_t sb  = sbase + (t % STAGES) * STAGE_B;
        const uint32_t bA0 = sb;
        const uint32_t bB0 = sb + TPB;
        const uint32_t bB1 = sb + 2 * TPB;   // TERMS==2 only

        #pragma unroll
        for (int kk = 0; kk < BKK / 16; kk++) {
            uint32_t a0[MI][4];
            uint32_t b0[NI][2], b1[NI][2];
            #pragma unroll
            for (int mi = 0; mi < MI; mi++) {
                uint32_t roff = (uint32_t)(wm * WM + mi * 16 + mrow) * PITCH +
                                mcolb + kk * 32;
                ldmatrix_x4(a0[mi], bA0 + roff);
            }
            #pragma unroll
            for (int nj = 0; nj < NJ; nj++) {
                uint32_t roff = (uint32_t)(wn * WN + nj * 16 + mrow) * PITCH +
                                mcolb + kk * 32;
                uint32_t r[4];
                ldmatrix_x4(r, bB0 + roff);
                b0[nj * 2][0]     = r[0]; b0[nj * 2][1]     = r[2];
                b0[nj * 2 + 1][0] = r[1]; b0[nj * 2 + 1][1] = r[3];
                if (TERMS == 2) {
                    ldmatrix_x4(r, bB1 + roff);
                    b1[nj * 2][0]     = r[0]; b1[nj * 2][1]     = r[2];
                    b1[nj * 2 + 1][0] = r[1]; b1[nj * 2 + 1][1] = r[3];
                }
            }
            #pragma unroll
            for (int mi = 0; mi < MI; mi++)
                #pragma unroll
                for (int ni = 0; ni < NI; ni++) {
                    mma_f16(acc[mi][ni], a0[mi], b0[ni]);
                    if (TERMS == 2) mma_f16(acc[mi][ni], a0[mi], b1[ni]);
                }
        }
        __syncthreads();
    }

    // ---- epilogue ----
    const int trow = lid >> 2;
    const int tcol = (lid & 3) * 2;
    #pragma unroll
    for (int mi = 0; mi < MI; mi++) {
        const int row = m0 + wm * WM + mi * 16 + trow;
        #pragma unroll
        for (int ni = 0; ni < NI; ni++) {
            const int col = n0 + wn * WN + ni * 8 + tcol;
            if (SPLITOUT) {
                #pragma unroll
                for (int h = 0; h < 2; h++) {
                    const int rr = row + h * 8;
                    __half2 hv(__float2half(acc[mi][ni][h * 2 + 0]),
                               __float2half(acc[mi][ni][h * 2 + 1]));
                    *reinterpret_cast<__half2*>(&Chi[(size_t)rr * D_DIM + col]) = hv;
                }
            } else {
                float b0v = bias[col], b1v = bias[col + 1];
                float2 v0 = {acc[mi][ni][0] + b0v, acc[mi][ni][1] + b1v};
                float2 v1 = {acc[mi][ni][2] + b0v, acc[mi][ni][3] + b1v};
                *reinterpret_cast<float2*>(&C[(size_t)row * D_DIM + col]) = v0;
                *reinterpret_cast<float2*>(&C[(size_t)(row + 8) * D_DIM + col]) = v1;
            }
        }
    }
}

// ------------------------- host launcher -------------------------
#define SMEM_G1 (3 * 3 * 64 * PITCH)    // 82944  (3 stages, 3 tiles, BT=64)
#define SMEM_G2 (3 * 2 * 128 * PITCH)   // 110592 (3 stages, 2 tiles, BT=128)

extern "C" void kernel_launch(void* const* d_in, const int* in_sizes, int n_in,
                              void* d_out, int out_size) {
    // 0 query, 1 key, 2 value, 3 mask, 4 Wq, 5 bq, 6 Wk, 7 bk, 8 Wv, 9 bv, 10 Wo, 11 bo
    const float* value = (const float*)d_in[2];
    const float* Wv    = (const float*)d_in[8];
    const float* bv    = (const float*)d_in[9];
    const float* Wo    = (const float*)d_in[10];
    const float* bo    = (const float*)d_in[11];
    float* out = (float*)d_out;

    void *pVh, *pAoh, *pBvhi, *pBvlo, *pWhi, *pbias;
    cudaGetSymbolAddress(&pVh, g_Vh);
    cudaGetSymbolAddress(&pAoh, g_Aoh);
    cudaGetSymbolAddress(&pBvhi, g_Bvhi);
    cudaGetSymbolAddress(&pBvlo, g_Bvlo);
    cudaGetSymbolAddress(&pWhi, g_Whi);
    cudaGetSymbolAddress(&pbias, g_bias);

    cudaFuncSetAttribute((const void*)gemm_nt<64, 32, 32, 2, 3, true>,
                         cudaFuncAttributeMaxDynamicSharedMemorySize, SMEM_G1);
    cudaFuncSetAttribute((const void*)gemm_nt<128, 64, 64, 1, 3, false>,
                         cudaFuncAttributeMaxDynamicSharedMemorySize, SMEM_G2);

    // conversions
    {
        int n4 = (D_DIM * D_DIM) / 4;
        f32_to_f16_v4<<<n4 / 256, 256>>>((const float4*)Wo, (uint32_t*)pAoh, n4);
    }
    {
        dim3 blk(32, 8), grd(D_DIM / 32, D_DIM / 32);
        transpose_split_f16<<<grd, blk>>>(Wv, (__half*)pBvhi, (__half*)pBvlo);
    }
    {
        int n4 = (ROWS * D_DIM) / 4;
        f32_to_f16_v4<<<n4 / 256, 256>>>((const float4*)value, (uint32_t*)pVh, n4);
    }
    fuse_bias<<<D_DIM, 256>>>(Wo, bv, bo);

    // GEMM1: W = fp16(Wo) @ (Wvhi + Wvlo)  -> fp16 Whi   (2-term)
    {
        dim3 grid(D_DIM / 64, D_DIM / 64);
        gemm_nt<64, 32, 32, 2, 3, true><<<grid, 128, SMEM_G1>>>(
            (const __half*)pAoh,
            (const __half*)pBvhi, (const __half*)pBvlo,
            nullptr, (__half*)pWhi, nullptr);
    }

    // GEMM2: out = Vh @ Whi^T + bias  (1-term, 64x64 warp tiles)
    {
        dim3 grid(D_DIM / 128, ROWS / 128);
        gemm_nt<128, 64, 64, 1, 3, false><<<grid, 128, SMEM_G2>>>(
            (const __half*)pVh,
            (const __half*)pWhi, nullptr,
            out, nullptr, (const float*)pbias);
    }
}

// round 9
// speedup vs baseline: 8.7153x; 1.1709x over previous
#include <cuda_runtime.h>
#include <cuda_fp16.h>
#include <cstdint>
#include <cstddef>

#define D_DIM 1024
#define ROWS  4096   // B*S

// ------------------------- device scratch -------------------------
__device__ __half g_Vh  [ROWS * D_DIM];     // fp16(value)
__device__ __half g_Aoh [D_DIM * D_DIM];    // fp16(Wo)      [m][k]
__device__ __half g_Bvh [D_DIM * D_DIM];    // fp16(Wv^T)    [n][k]
__device__ __half g_Whi [D_DIM * D_DIM];    // fp16(W = Wo@Wv) [n][k]
__device__ float  g_bias[D_DIM];            // Wo@bv + bo

// ------------------------- helpers -------------------------
__device__ __forceinline__ uint32_t smem_u32(const void* p) {
    uint32_t a;
    asm("{ .reg .u64 t; cvta.to.shared.u64 t, %1; cvt.u32.u64 %0, t; }"
        : "=r"(a) : "l"(p));
    return a;
}

__device__ __forceinline__ void ldmatrix_x4(uint32_t* r, uint32_t addr) {
    asm volatile("ldmatrix.sync.aligned.m8n8.x4.shared.b16 {%0,%1,%2,%3}, [%4];"
                 : "=r"(r[0]), "=r"(r[1]), "=r"(r[2]), "=r"(r[3]) : "r"(addr));
}

__device__ __forceinline__ void mma_f16(float* d, const uint32_t* a,
                                        const uint32_t* b) {
    asm volatile(
        "mma.sync.aligned.m16n8k16.row.col.f32.f16.f16.f32 "
        "{%0,%1,%2,%3}, {%4,%5,%6,%7}, {%8,%9}, {%0,%1,%2,%3};"
        : "+f"(d[0]), "+f"(d[1]), "+f"(d[2]), "+f"(d[3])
        : "r"(a[0]), "r"(a[1]), "r"(a[2]), "r"(a[3]), "r"(b[0]), "r"(b[1]));
}

__device__ __forceinline__ void cp_async16(uint32_t dst, const void* src) {
    asm volatile("cp.async.cg.shared.global [%0], [%1], 16;"
                 :: "r"(dst), "l"(src) : "memory");
}

// ------------------------- conversion kernels -------------------------
__global__ void f32_to_f16_v4(const float4* __restrict__ in,
                              uint32_t* __restrict__ out, int n4) {
    int i = blockIdx.x * blockDim.x + threadIdx.x;
    if (i >= n4) return;
    float4 x = in[i];
    __half2 h0(__float2half(x.x), __float2half(x.y));
    __half2 h1(__float2half(x.z), __float2half(x.w));
    out[2 * i]     = *reinterpret_cast<uint32_t*>(&h0);
    out[2 * i + 1] = *reinterpret_cast<uint32_t*>(&h1);
}

// Row-block fused: Aoh[row][*] = fp16(Wo[row][*]); g_bias[row] = Wo[row]·bv + bo[row]
__global__ void convert_wo_bias(const float* __restrict__ Wo,
                                const float* __restrict__ bv,
                                const float* __restrict__ bo,
                                __half* __restrict__ Aoh) {
    __shared__ float red[8];
    const int row = blockIdx.x;
    const int tid = threadIdx.x;
    float4 a = ((const float4*)(Wo + (size_t)row * D_DIM))[tid];
    float4 b = ((const float4*)bv)[tid];
    // write fp16 row
    __half2 h0(__float2half(a.x), __float2half(a.y));
    __half2 h1(__float2half(a.z), __float2half(a.w));
    uint2 pk = {*reinterpret_cast<uint32_t*>(&h0), *reinterpret_cast<uint32_t*>(&h1)};
    ((uint2*)(Aoh + (size_t)row * D_DIM))[tid] = pk;
    // bias reduction
    float s = a.x * b.x + a.y * b.y + a.z * b.z + a.w * b.w;
    #pragma unroll
    for (int o = 16; o > 0; o >>= 1)
        s += __shfl_down_sync(0xFFFFFFFFu, s, o);
    if ((tid & 31) == 0) red[tid >> 5] = s;
    __syncthreads();
    if (tid < 8) {
        s = red[tid];
        #pragma unroll
        for (int o = 4; o > 0; o >>= 1)
            s += __shfl_down_sync(0xFFu, s, o);
        if (tid == 0) g_bias[row] = s + bo[row];
    }
}

// Wv[k][n] -> out[n][k] fp16 (transpose + convert)
__global__ void transpose_f16(const float* __restrict__ in,
                              __half* __restrict__ out) {
    __shared__ float tile[32][33];
    int x = blockIdx.x * 32 + threadIdx.x;
    int y = blockIdx.y * 32;
    #pragma unroll
    for (int j = threadIdx.y; j < 32; j += 8)
        tile[j][threadIdx.x] = in[(size_t)(y + j) * D_DIM + x];
    __syncthreads();
    int ox = blockIdx.y * 32 + threadIdx.x;
    int oyb = blockIdx.x * 32;
    #pragma unroll
    for (int j = threadIdx.y; j < 32; j += 8)
        out[(size_t)(oyb + j) * D_DIM + ox] = __float2half(tile[threadIdx.x][j]);
}

// ------------------------- NT GEMM (mma.sync fp16, fp32 accum) ------------
// C[m][n] = sum_k A0[m,k] * B0[n,k]
// CTA tile BT x BT; warp tile WM x WN; BK=64; STAGES-deep cp.async.
// SPLITOUT: epilogue writes fp16(result) to Chi instead of fp32 C (+bias).
#define BKK   64
#define PITCH 144                            // 128B payload + 16B pad

template <int BT, int WM, int WN, int STAGES, bool SPLITOUT>
__global__ void __launch_bounds__((BT / WM) * (BT / WN) * 32, 2)
gemm_nt(const __half* __restrict__ A0, const __half* __restrict__ B0,
        float* __restrict__ C, __half* __restrict__ Chi,
        const float* __restrict__ bias) {
    constexpr int NWX     = BT / WN;         // warps along N
    constexpr int MI      = WM / 16;
    constexpr int NI      = WN / 8;
    constexpr int NJ      = WN / 16;
    constexpr int TPB     = BT * PITCH;
    constexpr int STAGE_B = 2 * TPB;
    constexpr int NT      = (BT / WM) * NWX * 32;
    constexpr int CHK     = (BT * 8) / NT;   // 16B chunks / thread / tile
    constexpr int T       = D_DIM / BKK;     // 16 k-tiles

    extern __shared__ __align__(128) char smem[];
    const uint32_t sbase = smem_u32(smem);

    const int tid = threadIdx.x;
    const int wid = tid >> 5;
    const int lid = tid & 31;
    const int wm  = wid / NWX;
    const int wn  = wid % NWX;
    const int m0  = blockIdx.y * BT;
    const int n0  = blockIdx.x * BT;

    const __half* gpA = A0 + (size_t)m0 * D_DIM;
    const __half* gpB = B0 + (size_t)n0 * D_DIM;

    // ldmatrix lane geometry
    const int mat   = lid >> 3;
    const int mrow  = ((mat & 1) << 3) + (lid & 7);
    const int mcolb = (mat >> 1) << 4;

    float acc[MI][NI][4];
    #pragma unroll
    for (int i = 0; i < MI; i++)
        #pragma unroll
        for (int j = 0; j < NI; j++)
            #pragma unroll
            for (int q = 0; q < 4; q++) acc[i][j][q] = 0.f;

    auto issue = [&](int t) {
        const uint32_t sb = sbase + (t % STAGES) * STAGE_B;
        const int k0 = t * BKK;
        #pragma unroll
        for (int i = 0; i < CHK; i++) {
            const int c = tid + i * NT;
            const int r = c >> 3, cc = c & 7;
            cp_async16(sb + r * PITCH + cc * 16,
                       gpA + (size_t)r * D_DIM + k0 + cc * 8);
            cp_async16(sb + TPB + r * PITCH + cc * 16,
                       gpB + (size_t)r * D_DIM + k0 + cc * 8);
        }
    };

    #pragma unroll
    for (int t = 0; t < STAGES - 1; t++) {
        issue(t);
        asm volatile("cp.async.commit_group;" ::: "memory");
    }

    for (int t = 0; t < T; t++) {
        asm volatile("cp.async.wait_group %0;" :: "n"(STAGES - 2) : "memory");
        __syncthreads();

        if (t + STAGES - 1 < T) issue(t + STAGES - 1);
        asm volatile("cp.async.commit_group;" ::: "memory");

        const uint32_t bA = sbase + (t % STAGES) * STAGE_B;
        const uint32_t bB = bA + TPB;

        #pragma unroll
        for (int kk = 0; kk < BKK / 16; kk++) {
            uint32_t a0[MI][4];
            uint32_t b0[NI][2];
            #pragma unroll
            for (int mi = 0; mi < MI; mi++) {
                uint32_t roff = (uint32_t)(wm * WM + mi * 16 + mrow) * PITCH +
                                mcolb + kk * 32;
                ldmatrix_x4(a0[mi], bA + roff);
            }
            #pragma unroll
            for (int nj = 0; nj < NJ; nj++) {
                uint32_t roff = (uint32_t)(wn * WN + nj * 16 + mrow) * PITCH +
                                mcolb + kk * 32;
                uint32_t r[4];
                ldmatrix_x4(r, bB + roff);
                b0[nj * 2][0]     = r[0]; b0[nj * 2][1]     = r[2];
                b0[nj * 2 + 1][0] = r[1]; b0[nj * 2 + 1][1] = r[3];
            }
            #pragma unroll
            for (int mi = 0; mi < MI; mi++)
                #pragma unroll
                for (int ni = 0; ni < NI; ni++)
                    mma_f16(acc[mi][ni], a0[mi], b0[ni]);
        }
        __syncthreads();
    }

    // ---- epilogue ----
    const int trow = lid >> 2;
    const int tcol = (lid & 3) * 2;
    #pragma unroll
    for (int mi = 0; mi < MI; mi++) {
        const int row = m0 + wm * WM + mi * 16 + trow;
        #pragma unroll
        for (int ni = 0; ni < NI; ni++) {
            const int col = n0 + wn * WN + ni * 8 + tcol;
            if (SPLITOUT) {
                #pragma unroll
                for (int h = 0; h < 2; h++) {
                    const int rr = row + h * 8;
                    __half2 hv(__float2half(acc[mi][ni][h * 2 + 0]),
                               __float2half(acc[mi][ni][h * 2 + 1]));
                    *reinterpret_cast<__half2*>(&Chi[(size_t)rr * D_DIM + col]) = hv;
                }
            } else {
                float b0v = bias[col], b1v = bias[col + 1];
                float2 v0 = {acc[mi][ni][0] + b0v, acc[mi][ni][1] + b1v};
                float2 v1 = {acc[mi][ni][2] + b0v, acc[mi][ni][3] + b1v};
                *reinterpret_cast<float2*>(&C[(size_t)row * D_DIM + col]) = v0;
                *reinterpret_cast<float2*>(&C[(size_t)(row + 8) * D_DIM + col]) = v1;
            }
        }
    }
}

// ------------------------- host launcher -------------------------
#define SMEM_G1 (3 * 2 * 64 * PITCH)    // 55296  (3 stages, 2 tiles, BT=64)
#define SMEM_G2 (3 * 2 * 128 * PITCH)   // 110592 (3 stages, 2 tiles, BT=128)

extern "C" void kernel_launch(void* const* d_in, const int* in_sizes, int n_in,
                              void* d_out, int out_size) {
    // 0 query, 1 key, 2 value, 3 mask, 4 Wq, 5 bq, 6 Wk, 7 bk, 8 Wv, 9 bv, 10 Wo, 11 bo
    const float* value = (const float*)d_in[2];
    const float* Wv    = (const float*)d_in[8];
    const float* bv    = (const float*)d_in[9];
    const float* Wo    = (const float*)d_in[10];
    const float* bo    = (const float*)d_in[11];
    float* out = (float*)d_out;

    void *pVh, *pAoh, *pBvh, *pWhi, *pbias;
    cudaGetSymbolAddress(&pVh, g_Vh);
    cudaGetSymbolAddress(&pAoh, g_Aoh);
    cudaGetSymbolAddress(&pBvh, g_Bvh);
    cudaGetSymbolAddress(&pWhi, g_Whi);
    cudaGetSymbolAddress(&pbias, g_bias);

    cudaFuncSetAttribute((const void*)gemm_nt<64, 32, 32, 3, true>,
                         cudaFuncAttributeMaxDynamicSharedMemorySize, SMEM_G1);
    cudaFuncSetAttribute((const void*)gemm_nt<128, 64, 64, 3, false>,
                         cudaFuncAttributeMaxDynamicSharedMemorySize, SMEM_G2);

    // conversions (Wo convert + bias GEMV fused; Wv transpose)
    convert_wo_bias<<<D_DIM, 256>>>(Wo, bv, bo, (__half*)pAoh);
    {
        dim3 blk(32, 8), grd(D_DIM / 32, D_DIM / 32);
        transpose_f16<<<grd, blk>>>(Wv, (__half*)pBvh);
    }

    // GEMM1: W = f16(Wo) @ f16(Wv^T)  -> fp16 Whi
    {
        dim3 grid(D_DIM / 64, D_DIM / 64);
        gemm_nt<64, 32, 32, 3, true><<<grid, 128, SMEM_G1>>>(
            (const __half*)pAoh, (const __half*)pBvh,
            nullptr, (__half*)pWhi, nullptr);
    }

    // V convert (independent of GEMM1 inputs; placed here to shrink the gap
    // between GEMM1 and GEMM2 dependencies)
    {
        int n4 = (ROWS * D_DIM) / 4;
        f32_to_f16_v4<<<n4 / 256, 256>>>((const float4*)value, (uint32_t*)pVh, n4);
    }

    // GEMM2: out = Vh @ Whi^T + bias
    {
        dim3 grid(D_DIM / 128, ROWS / 128);
        gemm_nt<128, 64, 64, 3, false><<<grid, 128, SMEM_G2>>>(
            (const __half*)pVh, (const __half*)pWhi,
            out, nullptr, (const float*)pbias);
    }
}

// round 10
// speedup vs baseline: 9.0039x; 1.0331x over previous
#include <cuda_runtime.h>
#include <cuda_fp16.h>
#include <cstdint>
#include <cstddef>

#define D_DIM 1024
#define ROWS  4096   // B*S

// ------------------------- device scratch -------------------------
__device__ __half g_Vh  [ROWS * D_DIM];     // fp16(value)
__device__ __half g_Aoh [D_DIM * D_DIM];    // fp16(Wo)      [m][k]
__device__ __half g_Bvh [D_DIM * D_DIM];    // fp16(Wv^T)    [n][k]
__device__ __half g_Whi [D_DIM * D_DIM];    // fp16(W = Wo@Wv) [n][k]
__device__ float  g_bias[D_DIM];            // Wo@bv + bo

// ------------------------- helpers -------------------------
__device__ __forceinline__ uint32_t smem_u32(const void* p) {
    uint32_t a;
    asm("{ .reg .u64 t; cvta.to.shared.u64 t, %1; cvt.u32.u64 %0, t; }"
        : "=r"(a) : "l"(p));
    return a;
}

__device__ __forceinline__ void ldmatrix_x4(uint32_t* r, uint32_t addr) {
    asm volatile("ldmatrix.sync.aligned.m8n8.x4.shared.b16 {%0,%1,%2,%3}, [%4];"
                 : "=r"(r[0]), "=r"(r[1]), "=r"(r[2]), "=r"(r[3]) : "r"(addr));
}

__device__ __forceinline__ void mma_f16(float* d, const uint32_t* a,
                                        const uint32_t* b) {
    asm volatile(
        "mma.sync.aligned.m16n8k16.row.col.f32.f16.f16.f32 "
        "{%0,%1,%2,%3}, {%4,%5,%6,%7}, {%8,%9}, {%0,%1,%2,%3};"
        : "+f"(d[0]), "+f"(d[1]), "+f"(d[2]), "+f"(d[3])
        : "r"(a[0]), "r"(a[1]), "r"(a[2]), "r"(a[3]), "r"(b[0]), "r"(b[1]));
}

__device__ __forceinline__ void cp_async16(uint32_t dst, const void* src) {
    asm volatile("cp.async.cg.shared.global [%0], [%1], 16;"
                 :: "r"(dst), "l"(src) : "memory");
}

// ------------------------- fused conversion mega-kernel -------------------
// blockIdx.x partition (256 threads each):
//   [0, 1024)     : Wo row convert + bias GEMV          (row = bid)
//   [1024, 2048)  : Wv 32x32 transpose tile             (tile = bid-1024)
//   [2048, 4096)  : V fp32->fp16, 512 float4 per block  (chunk = bid-2048)
__global__ void __launch_bounds__(256)
convert_all(const float* __restrict__ Wo, const float* __restrict__ bv,
            const float* __restrict__ bo, const float* __restrict__ Wv,
            const float* __restrict__ value,
            __half* __restrict__ Aoh, __half* __restrict__ Bvh,
            uint32_t* __restrict__ Vh) {
    __shared__ float sm[33 * 32];     // transpose tile / bias reduction
    const int bid = blockIdx.x;
    const int tid = threadIdx.x;

    if (bid < 1024) {
        // ---- Wo convert + bias GEMV (one row) ----
        const int row = bid;
        float4 a = ((const float4*)(Wo + (size_t)row * D_DIM))[tid];
        float4 b = ((const float4*)bv)[tid];
        __half2 h0(__float2half(a.x), __float2half(a.y));
        __half2 h1(__float2half(a.z), __float2half(a.w));
        uint2 pk = {*reinterpret_cast<uint32_t*>(&h0),
                    *reinterpret_cast<uint32_t*>(&h1)};
        ((uint2*)(Aoh + (size_t)row * D_DIM))[tid] = pk;
        float s = a.x * b.x + a.y * b.y + a.z * b.z + a.w * b.w;
        #pragma unroll
        for (int o = 16; o > 0; o >>= 1)
            s += __shfl_down_sync(0xFFFFFFFFu, s, o);
        if ((tid & 31) == 0) sm[tid >> 5] = s;
        __syncthreads();
        if (tid < 8) {
            s = sm[tid];
            #pragma unroll
            for (int o = 4; o > 0; o >>= 1)
                s += __shfl_down_sync(0xFFu, s, o);
            if (tid == 0) g_bias[row] = s + bo[row];
        }
    } else if (bid < 2048) {
        // ---- Wv[k][n] -> Bvh[n][k] transpose tile ----
        const int t  = bid - 1024;
        const int bx = t & 31, by = t >> 5;
        const int tx = tid & 31, ty = tid >> 5;      // 32 x 8
        const int x = bx * 32 + tx;
        const int y = by * 32;
        #pragma unroll
        for (int j = ty; j < 32; j += 8)
            sm[j * 33 + tx] = Wv[(size_t)(y + j) * D_DIM + x];
        __syncthreads();
        const int ox  = by * 32 + tx;
        const int oyb = bx * 32;
        #pragma unroll
        for (int j = ty; j < 32; j += 8)
            Bvh[(size_t)(oyb + j) * D_DIM + ox] = __float2half(sm[tx * 33 + j]);
    } else {
        // ---- V fp32 -> fp16, 512 float4 per block ----
        const int base = (bid - 2048) * 512 + tid;
        #pragma unroll
        for (int u = 0; u < 2; u++) {
            const int i = base + u * 256;
            float4 x = ((const float4*)value)[i];
            __half2 h0(__float2half(x.x), __float2half(x.y));
            __half2 h1(__float2half(x.z), __float2half(x.w));
            Vh[2 * i]     = *reinterpret_cast<uint32_t*>(&h0);
            Vh[2 * i + 1] = *reinterpret_cast<uint32_t*>(&h1);
        }
    }
}

// ------------------------- NT GEMM (mma.sync fp16, fp32 accum) ------------
// C[m][n] = sum_k A0[m,k] * B0[n,k]
// CTA tile BT x BT; warp tile WM x WN; BK=64; STAGES-deep cp.async.
// SPLITOUT: epilogue writes fp16(result) to Chi instead of fp32 C (+bias).
#define BKK   64
#define PITCH 144                            // 128B payload + 16B pad

template <int BT, int WM, int WN, int STAGES, bool SPLITOUT>
__global__ void __launch_bounds__((BT / WM) * (BT / WN) * 32, 2)
gemm_nt(const __half* __restrict__ A0, const __half* __restrict__ B0,
        float* __restrict__ C, __half* __restrict__ Chi,
        const float* __restrict__ bias) {
    constexpr int NWX     = BT / WN;         // warps along N
    constexpr int MI      = WM / 16;
    constexpr int NI      = WN / 8;
    constexpr int NJ      = WN / 16;
    constexpr int TPB     = BT * PITCH;
    constexpr int STAGE_B = 2 * TPB;
    constexpr int NT      = (BT / WM) * NWX * 32;
    constexpr int CHK     = (BT * 8) / NT;   // 16B chunks / thread / tile
    constexpr int T       = D_DIM / BKK;     // 16 k-tiles

    extern __shared__ __align__(128) char smem[];
    const uint32_t sbase = smem_u32(smem);

    const int tid = threadIdx.x;
    const int wid = tid >> 5;
    const int lid = tid & 31;
    const int wm  = wid / NWX;
    const int wn  = wid % NWX;
    const int m0  = blockIdx.y * BT;
    const int n0  = blockIdx.x * BT;

    const __half* gpA = A0 + (size_t)m0 * D_DIM;
    const __half* gpB = B0 + (size_t)n0 * D_DIM;

    // ldmatrix lane geometry
    const int mat   = lid >> 3;
    const int mrow  = ((mat & 1) << 3) + (lid & 7);
    const int mcolb = (mat >> 1) << 4;

    float acc[MI][NI][4];
    #pragma unroll
    for (int i = 0; i < MI; i++)
        #pragma unroll
        for (int j = 0; j < NI; j++)
            #pragma unroll
            for (int q = 0; q < 4; q++) acc[i][j][q] = 0.f;

    auto issue = [&](int t) {
        const uint32_t sb = sbase + (t % STAGES) * STAGE_B;
        const int k0 = t * BKK;
        #pragma unroll
        for (int i = 0; i < CHK; i++) {
            const int c = tid + i * NT;
            const int r = c >> 3, cc = c & 7;
            cp_async16(sb + r * PITCH + cc * 16,
                       gpA + (size_t)r * D_DIM + k0 + cc * 8);
            cp_async16(sb + TPB + r * PITCH + cc * 16,
                       gpB + (size_t)r * D_DIM + k0 + cc * 8);
        }
    };

    #pragma unroll
    for (int t = 0; t < STAGES - 1; t++) {
        issue(t);
        asm volatile("cp.async.commit_group;" ::: "memory");
    }

    for (int t = 0; t < T; t++) {
        asm volatile("cp.async.wait_group %0;" :: "n"(STAGES - 2) : "memory");
        __syncthreads();

        if (t + STAGES - 1 < T) issue(t + STAGES - 1);
        asm volatile("cp.async.commit_group;" ::: "memory");

        const uint32_t bA = sbase + (t % STAGES) * STAGE_B;
        const uint32_t bB = bA + TPB;

        #pragma unroll
        for (int kk = 0; kk < BKK / 16; kk++) {
            uint32_t a0[MI][4];
            uint32_t b0[NI][2];
            #pragma unroll
            for (int mi = 0; mi < MI; mi++) {
                uint32_t roff = (uint32_t)(wm * WM + mi * 16 + mrow) * PITCH +
                                mcolb + kk * 32;
                ldmatrix_x4(a0[mi], bA + roff);
            }
            #pragma unroll
            for (int nj = 0; nj < NJ; nj++) {
                uint32_t roff = (uint32_t)(wn * WN + nj * 16 + mrow) * PITCH +
                                mcolb + kk * 32;
                uint32_t r[4];
                ldmatrix_x4(r, bB + roff);
                b0[nj * 2][0]     = r[0]; b0[nj * 2][1]     = r[2];
                b0[nj * 2 + 1][0] = r[1]; b0[nj * 2 + 1][1] = r[3];
            }
            #pragma unroll
            for (int mi = 0; mi < MI; mi++)
                #pragma unroll
                for (int ni = 0; ni < NI; ni++)
                    mma_f16(acc[mi][ni], a0[mi], b0[ni]);
        }
        __syncthreads();
    }

    // ---- epilogue ----
    const int trow = lid >> 2;
    const int tcol = (lid & 3) * 2;
    #pragma unroll
    for (int mi = 0; mi < MI; mi++) {
        const int row = m0 + wm * WM + mi * 16 + trow;
        #pragma unroll
        for (int ni = 0; ni < NI; ni++) {
            const int col = n0 + wn * WN + ni * 8 + tcol;
            if (SPLITOUT) {
                #pragma unroll
                for (int h = 0; h < 2; h++) {
                    const int rr = row + h * 8;
                    __half2 hv(__float2half(acc[mi][ni][h * 2 + 0]),
                               __float2half(acc[mi][ni][h * 2 + 1]));
                    *reinterpret_cast<__half2*>(&Chi[(size_t)rr * D_DIM + col]) = hv;
                }
            } else {
                float b0v = bias[col], b1v = bias[col + 1];
                float2 v0 = {acc[mi][ni][0] + b0v, acc[mi][ni][1] + b1v};
                float2 v1 = {acc[mi][ni][2] + b0v, acc[mi][ni][3] + b1v};
                *reinterpret_cast<float2*>(&C[(size_t)row * D_DIM + col]) = v0;
                *reinterpret_cast<float2*>(&C[(size_t)(row + 8) * D_DIM + col]) = v1;
            }
        }
    }
}

// ------------------------- host launcher -------------------------
#define SMEM_G1 (3 * 2 * 64 * PITCH)    // 55296  (3 stages, 2 tiles, BT=64)
#define SMEM_G2 (3 * 2 * 128 * PITCH)   // 110592 (3 stages, 2 tiles, BT=128)

extern "C" void kernel_launch(void* const* d_in, const int* in_sizes, int n_in,
                              void* d_out, int out_size) {
    // 0 query, 1 key, 2 value, 3 mask, 4 Wq, 5 bq, 6 Wk, 7 bk, 8 Wv, 9 bv, 10 Wo, 11 bo
    const float* value = (const float*)d_in[2];
    const float* Wv    = (const float*)d_in[8];
    const float* bv    = (const float*)d_in[9];
    const float* Wo    = (const float*)d_in[10];
    const float* bo    = (const float*)d_in[11];
    float* out = (float*)d_out;

    void *pVh, *pAoh, *pBvh, *pWhi, *pbias;
    cudaGetSymbolAddress(&pVh, g_Vh);
    cudaGetSymbolAddress(&pAoh, g_Aoh);
    cudaGetSymbolAddress(&pBvh, g_Bvh);
    cudaGetSymbolAddress(&pWhi, g_Whi);
    cudaGetSymbolAddress(&pbias, g_bias);

    cudaFuncSetAttribute((const void*)gemm_nt<64, 32, 32, 3, true>,
                         cudaFuncAttributeMaxDynamicSharedMemorySize, SMEM_G1);
    cudaFuncSetAttribute((const void*)gemm_nt<128, 64, 64, 3, false>,
                         cudaFuncAttributeMaxDynamicSharedMemorySize, SMEM_G2);

    // 1) all conversions in one launch:
    //    Wo->fp16 + bias GEMV, Wv transpose->fp16, V->fp16
    convert_all<<<4096, 256>>>(Wo, bv, bo, Wv, value,
                               (__half*)pAoh, (__half*)pBvh, (uint32_t*)pVh);

    // 2) GEMM1: W = f16(Wo) @ f16(Wv^T)  -> fp16 Whi
    {
        dim3 grid(D_DIM / 64, D_DIM / 64);
        gemm_nt<64, 32, 32, 3, true><<<grid, 128, SMEM_G1>>>(
            (const __half*)pAoh, (const __half*)pBvh,
            nullptr, (__half*)pWhi, nullptr);
    }

    // 3) GEMM2: out = Vh @ Whi^T + bias
    {
        dim3 grid(D_DIM / 128, ROWS / 128);
        gemm_nt<128, 64, 64, 3, false><<<grid, 128, SMEM_G2>>>(
            (const __half*)pVh, (const __half*)pWhi,
            out, nullptr, (const float*)pbias);
    }
}